// round 1
// baseline (speedup 1.0000x reference)
#include <cuda_runtime.h>
#include <math.h>

// Problem constants
#define BB 2
#define SS 2048
#define DD 2048
#define HH 16
#define FF 128
#define EPSV 1e-6f

// ---------------- scratch (static device memory; no allocations) ----------------
__device__ float g_wt0[2048 * 2048];
__device__ float g_wt1[2048 * 2048];
__device__ float g_wt2[2048 * 2048];
__device__ float g_q[4096 * 2048];
__device__ float g_k[4096 * 2048];
__device__ float g_v[4096 * 2048];
__device__ float g_attn[4096 * 2048];
__device__ float g_sc[134217728];   // 32 * 2048 * 2048 scores, 536 MB
__device__ float g_cos[2048 * 64];
__device__ float g_sin[2048 * 64];

// ---------------- RoPE table (match reference's fp32 angle, accurate sin/cos) ----
__global__ void rope_table_kernel(float* __restrict__ cosT, float* __restrict__ sinT) {
    int idx = blockIdx.x * 256 + threadIdx.x;
    if (idx >= 2048 * 64) return;
    int p = idx / 64, i = idx % 64;
    float freq = (float)(1.0 / pow(10000.0, (double)i / 64.0));
    float a = (float)p * freq;                  // fp32 product, as in reference
    cosT[idx] = (float)cos((double)a);
    sinT[idx] = (float)sin((double)a);
}

// ---------------- weight transpose: W[H,D,F] -> Wt[D, H*F] ----------------------
__global__ void transpose_w_kernel(const float* __restrict__ W, float* __restrict__ Wt) {
    int idx = blockIdx.x * 256 + threadIdx.x;   // over D*H*F = 4M
    int n = idx & 2047;
    int d = idx >> 11;
    int h = n >> 7, f = n & 127;
    Wt[idx] = W[(h * 2048 + d) * 128 + f];
}

// ---------------- generic tiled SGEMM (NN / NT), strided batch, fused bias ------
// C[M,N] = alpha * A[M,K] * op(B) + bias[n],  op(B)=B[K,N] (NN) or B[N,K] (NT)
// batch offset: off = (z / zdiv) * s1 + (z % zdiv) * s2
template <bool TB>
__global__ __launch_bounds__(256)
void sgemm_kernel(const float* __restrict__ A, const float* __restrict__ Bm,
                  float* __restrict__ C, const float* __restrict__ bias,
                  int M, int N, int K, int lda, int ldb, int ldc,
                  int zdivA, long sA1, long sA2,
                  int zdivB, long sB1, long sB2,
                  int zdivC, long sC1, long sC2,
                  float alpha) {
    int z = blockIdx.z;
    A += (long)(z / zdivA) * sA1 + (long)(z % zdivA) * sA2;
    Bm += (long)(z / zdivB) * sB1 + (long)(z % zdivB) * sB2;
    C += (long)(z / zdivC) * sC1 + (long)(z % zdivC) * sC2;

    __shared__ float As[8][128];
    __shared__ float Bs[8][132];

    const int tid = threadIdx.x;
    const int tx = tid & 15, ty = tid >> 4;
    const int bm = blockIdx.y * 128, bn = blockIdx.x * 128;

    float acc[8][8];
#pragma unroll
    for (int i = 0; i < 8; i++)
#pragma unroll
        for (int j = 0; j < 8; j++) acc[i][j] = 0.f;

    const int arow = tid >> 1, ak4 = (tid & 1) * 4;

    for (int k0 = 0; k0 < K; k0 += 8) {
        float4 av = *(const float4*)(A + (long)(bm + arow) * lda + k0 + ak4);
        As[ak4 + 0][arow] = av.x;
        As[ak4 + 1][arow] = av.y;
        As[ak4 + 2][arow] = av.z;
        As[ak4 + 3][arow] = av.w;
        if (!TB) {
            int bk = tid >> 5, bc = (tid & 31) * 4;
            float4 bv = *(const float4*)(Bm + (long)(k0 + bk) * ldb + bn + bc);
            Bs[bk][bc + 0] = bv.x;
            Bs[bk][bc + 1] = bv.y;
            Bs[bk][bc + 2] = bv.z;
            Bs[bk][bc + 3] = bv.w;
        } else {
            int brow = tid >> 1, bk4 = (tid & 1) * 4;
            float4 bv = *(const float4*)(Bm + (long)(bn + brow) * ldb + k0 + bk4);
            Bs[bk4 + 0][brow] = bv.x;
            Bs[bk4 + 1][brow] = bv.y;
            Bs[bk4 + 2][brow] = bv.z;
            Bs[bk4 + 3][brow] = bv.w;
        }
        __syncthreads();
#pragma unroll
        for (int kk = 0; kk < 8; kk++) {
            float a[8], b[8];
#pragma unroll
            for (int i = 0; i < 8; i++) a[i] = As[kk][ty * 8 + i];
#pragma unroll
            for (int j = 0; j < 8; j++) b[j] = Bs[kk][tx * 8 + j];
#pragma unroll
            for (int i = 0; i < 8; i++)
#pragma unroll
                for (int j = 0; j < 8; j++) acc[i][j] += a[i] * b[j];
        }
        __syncthreads();
    }

#pragma unroll
    for (int i = 0; i < 8; i++) {
        int row = bm + ty * 8 + i;
#pragma unroll
        for (int j = 0; j < 8; j++) {
            int col = bn + tx * 8 + j;
            float v = acc[i][j] * alpha;
            if (bias) v += bias[col];
            C[(long)row * ldc + col] = v;
        }
    }
}

// ---------------- fused RMSNorm + RoPE (per (b,p,h) row of 128) ------------------
__global__ void norm_rope_kernel(float* __restrict__ x, const float* __restrict__ w,
                                 const float* __restrict__ cosT, const float* __restrict__ sinT) {
    long r = blockIdx.x;            // 0 .. B*S*H-1
    int h = (int)(r & 15);
    long row = r >> 4;              // b*S + p
    int p = (int)(row & (SS - 1));
    float* ptr = x + row * 2048 + h * 128;
    int f = threadIdx.x;

    float v = ptr[f];
    float ss = v * v;
#pragma unroll
    for (int o = 16; o; o >>= 1) ss += __shfl_xor_sync(0xffffffffu, ss, o);
    __shared__ float red[4];
    if ((f & 31) == 0) red[f >> 5] = ss;
    __syncthreads();
    ss = red[0] + red[1] + red[2] + red[3];

    float rms = sqrtf(ss * (1.f / 128.f));
    float sv = v / (rms + EPSV) * w[f];

    __shared__ float sh[128];
    sh[f] = sv;
    __syncthreads();

    int i = f & 63;
    float c = cosT[p * 64 + i], s = sinT[p * 64 + i];
    float out = (f < 64) ? (sv * c - sh[f + 64] * s) : (sv * c + sh[f - 64] * s);
    ptr[f] = out;
}

// ---------------- row softmax over 2048 ------------------------------------------
__global__ __launch_bounds__(256)
void softmax_kernel(float* __restrict__ sc) {
    long row = blockIdx.x;
    float* p = sc + row * 2048;
    int t = threadIdx.x;

    float v[8];
    float m = -1e30f;
#pragma unroll
    for (int j = 0; j < 8; j++) {
        v[j] = p[t + 256 * j];
        m = fmaxf(m, v[j]);
    }
#pragma unroll
    for (int o = 16; o; o >>= 1) m = fmaxf(m, __shfl_xor_sync(0xffffffffu, m, o));
    __shared__ float redm[8];
    __shared__ float reds[8];
    if ((t & 31) == 0) redm[t >> 5] = m;
    __syncthreads();
    m = redm[0];
#pragma unroll
    for (int j = 1; j < 8; j++) m = fmaxf(m, redm[j]);

    float s = 0.f;
#pragma unroll
    for (int j = 0; j < 8; j++) {
        v[j] = expf(v[j] - m);
        s += v[j];
    }
#pragma unroll
    for (int o = 16; o; o >>= 1) s += __shfl_xor_sync(0xffffffffu, s, o);
    if ((t & 31) == 0) reds[t >> 5] = s;
    __syncthreads();
    s = reds[0];
#pragma unroll
    for (int j = 1; j < 8; j++) s += reds[j];

    float inv = 1.f / s;
#pragma unroll
    for (int j = 0; j < 8; j++) p[t + 256 * j] = v[j] * inv;
}

// ---------------- host orchestration ----------------------------------------------
extern "C" void kernel_launch(void* const* d_in, const int* in_sizes, int n_in,
                              void* d_out, int out_size) {
    const float* xq = (const float*)d_in[0];
    const float* xk = (const float*)d_in[1];
    const float* xv = (const float*)d_in[2];
    const float* WQ = (const float*)d_in[3];
    const float* WK = (const float*)d_in[4];
    const float* WV = (const float*)d_in[5];
    const float* WO = (const float*)d_in[6];
    const float* bQ = (const float*)d_in[7];
    const float* bK = (const float*)d_in[8];
    const float* bV = (const float*)d_in[9];
    const float* bO = (const float*)d_in[10];
    const float* qw = (const float*)d_in[11];
    const float* kw = (const float*)d_in[12];
    float* out = (float*)d_out;

    float *wt0, *wt1, *wt2, *qb, *kb, *vb, *ab, *sc, *ct, *st;
    cudaGetSymbolAddress((void**)&wt0, g_wt0);
    cudaGetSymbolAddress((void**)&wt1, g_wt1);
    cudaGetSymbolAddress((void**)&wt2, g_wt2);
    cudaGetSymbolAddress((void**)&qb, g_q);
    cudaGetSymbolAddress((void**)&kb, g_k);
    cudaGetSymbolAddress((void**)&vb, g_v);
    cudaGetSymbolAddress((void**)&ab, g_attn);
    cudaGetSymbolAddress((void**)&sc, g_sc);
    cudaGetSymbolAddress((void**)&ct, g_cos);
    cudaGetSymbolAddress((void**)&st, g_sin);

    const long M4 = 4194304;  // 2048*2048 (also S*ld per batch b)

    rope_table_kernel<<<(2048 * 64 + 255) / 256, 256>>>(ct, st);
    transpose_w_kernel<<<16384, 256>>>(WQ, wt0);
    transpose_w_kernel<<<16384, 256>>>(WK, wt1);
    transpose_w_kernel<<<16384, 256>>>(WV, wt2);

    // QKV projections: [4096,2048] x [2048,2048] + bias
    dim3 gProj(16, 32, 1);
    sgemm_kernel<false><<<gProj, 256>>>(xq, wt0, qb, bQ, 4096, 2048, 2048, 2048, 2048, 2048,
                                        1, 0, 0, 1, 0, 0, 1, 0, 0, 1.f);
    sgemm_kernel<false><<<gProj, 256>>>(xk, wt1, kb, bK, 4096, 2048, 2048, 2048, 2048, 2048,
                                        1, 0, 0, 1, 0, 0, 1, 0, 0, 1.f);
    sgemm_kernel<false><<<gProj, 256>>>(xv, wt2, vb, bV, 4096, 2048, 2048, 2048, 2048, 2048,
                                        1, 0, 0, 1, 0, 0, 1, 0, 0, 1.f);

    // RMSNorm + RoPE for q, k
    norm_rope_kernel<<<BB * SS * HH, 128>>>(qb, qw, ct, st);
    norm_rope_kernel<<<BB * SS * HH, 128>>>(kb, kw, ct, st);

    // scores[bh] = (1/sqrt(F)) * q_slice @ k_slice^T   (NT, batched over 32)
    dim3 gScore(16, 16, 32);
    sgemm_kernel<true><<<gScore, 256>>>(qb, kb, sc, nullptr, 2048, 2048, 128, 2048, 2048, 2048,
                                        16, M4, 128,
                                        16, M4, 128,
                                        1, M4, 0,
                                        0.08838834764831845f);

    // softmax over last dim
    softmax_kernel<<<32 * 2048, 256>>>(sc);

    // attn[bh] = P @ v_slice  (NN, batched over 32)
    dim3 gPV(1, 16, 32);
    sgemm_kernel<false><<<gPV, 256>>>(sc, vb, ab, nullptr, 2048, 128, 2048, 2048, 2048, 2048,
                                      1, M4, 0,
                                      16, M4, 128,
                                      16, M4, 128,
                                      1.f);

    // output projection: [4096,2048] x [2048,2048] + b_O
    sgemm_kernel<false><<<gProj, 256>>>(ab, WO, out, bO, 4096, 2048, 2048, 2048, 2048, 2048,
                                        1, 0, 0, 1, 0, 0, 1, 0, 0, 1.f);
}

// round 3
// speedup vs baseline: 1.8582x; 1.8582x over previous
#include <cuda_runtime.h>
#include <cuda_bf16.h>
#include <cstdint>
#include <math.h>

#define BB 2
#define SS 2048
#define DD 2048
#define HH 16
#define FF 128
#define EPSV 1e-6f

// ---------------- scratch (static device memory; no allocations) ----------------
__device__ float g_wt0[2048 * 2048];
__device__ float g_wt1[2048 * 2048];
__device__ float g_wt2[2048 * 2048];
__device__ float g_q[4096 * 2048];
__device__ float g_k[4096 * 2048];
__device__ float g_v[4096 * 2048];
__device__ float g_attn[4096 * 2048];
__device__ float g_sc[134217728];   // 32 * 2048 * 2048 scores
__device__ float g_cos[2048 * 64];
__device__ float g_sin[2048 * 64];

// ---------------- RoPE table -----------------------------------------------------
__global__ void rope_table_kernel(float* __restrict__ cosT, float* __restrict__ sinT) {
    int idx = blockIdx.x * 256 + threadIdx.x;
    if (idx >= 2048 * 64) return;
    int p = idx / 64, i = idx % 64;
    float freq = (float)(1.0 / pow(10000.0, (double)i / 64.0));
    float a = (float)p * freq;
    cosT[idx] = (float)cos((double)a);
    sinT[idx] = (float)sin((double)a);
}

// ---------------- weight transpose: W[H,D,F] -> Wt[D, H*F] -----------------------
__global__ void transpose_w_kernel(const float* __restrict__ W, float* __restrict__ Wt) {
    int idx = blockIdx.x * 256 + threadIdx.x;
    int n = idx & 2047;
    int d = idx >> 11;
    int h = n >> 7, f = n & 127;
    Wt[idx] = W[(h * 2048 + d) * 128 + f];
}

// ---------------- bf16 split helpers ---------------------------------------------
__device__ __forceinline__ uint32_t pack2(__nv_bfloat16 a, __nv_bfloat16 b) {
    __nv_bfloat162 h2;
    h2.x = a; h2.y = b;
    return *reinterpret_cast<uint32_t*>(&h2);
}

// split two floats into (hi-pair, lo-pair) packed words
__device__ __forceinline__ void split_pair(float e0, float e1, uint32_t& hi, uint32_t& lo) {
    __nv_bfloat16 h0 = __float2bfloat16_rn(e0);
    __nv_bfloat16 h1 = __float2bfloat16_rn(e1);
    float l0 = e0 - __bfloat162float(h0);
    float l1 = e1 - __bfloat162float(h1);
    hi = pack2(h0, h1);
    lo = pack2(__float2bfloat16_rn(l0), __float2bfloat16_rn(l1));
}

__device__ __forceinline__ void mma16816(float* c, uint32_t a0, uint32_t a1, uint32_t a2,
                                         uint32_t a3, uint32_t b0, uint32_t b1) {
    asm volatile(
        "mma.sync.aligned.m16n8k16.row.col.f32.bf16.bf16.f32 "
        "{%0,%1,%2,%3},{%4,%5,%6,%7},{%8,%9},{%0,%1,%2,%3};\n"
        : "+f"(c[0]), "+f"(c[1]), "+f"(c[2]), "+f"(c[3])
        : "r"(a0), "r"(a1), "r"(a2), "r"(a3), "r"(b0), "r"(b1));
}

// ---------------- split-bf16 tensor-core GEMM (NN/NT), batched, fused bias -------
// C[M,N] = alpha * A[M,K] * op(B) + bias, op(B)=B[K,N] (NN) or B[N,K] (NT)
// 128x128 block tile, K-chunk 32, 8 warps (2x4), warp tile 64x32, mma m16n8k16.
#define LDS_W 136
template <bool TB>
__global__ __launch_bounds__(256, 2)
void bgemm_kernel(const float* __restrict__ A, const float* __restrict__ Bm,
                  float* __restrict__ C, const float* __restrict__ bias,
                  int M, int N, int K, int lda, int ldb, int ldc,
                  int zdivA, long sA1, long sA2,
                  int zdivB, long sB1, long sB2,
                  int zdivC, long sC1, long sC2,
                  float alpha) {
    int z = blockIdx.z;
    A += (long)(z / zdivA) * sA1 + (long)(z % zdivA) * sA2;
    Bm += (long)(z / zdivB) * sB1 + (long)(z % zdivB) * sB2;
    C += (long)(z / zdivC) * sC1 + (long)(z % zdivC) * sC2;

    // bf16x2 pairs along k: [kpair][m or n], kpair 0..15 per 32-k chunk
    __shared__ uint32_t As_hi[16][LDS_W];
    __shared__ uint32_t As_lo[16][LDS_W];
    __shared__ uint32_t Bs_hi[16][LDS_W];
    __shared__ uint32_t Bs_lo[16][LDS_W];

    const int tid = threadIdx.x;
    const int lane = tid & 31;
    const int warp = tid >> 5;
    const int wm = (warp >> 2) * 64;   // warp row offset
    const int wn = (warp & 3) * 32;    // warp col offset
    const int g = lane >> 2;           // group id
    const int t4 = lane & 3;           // thread-in-group
    const int bm = blockIdx.y * 128, bn = blockIdx.x * 128;

    const int lm = tid & 127;          // row for A (and NT-B) loader
    const int kbA = (tid >> 7) * 16;   // fp32 k offset (0 or 16)

    float acc[4][4][4];
#pragma unroll
    for (int i = 0; i < 4; i++)
#pragma unroll
        for (int j = 0; j < 4; j++)
#pragma unroll
            for (int r = 0; r < 4; r++) acc[i][j][r] = 0.f;

    for (int k0 = 0; k0 < K; k0 += 32) {
        // ---- load A tile: 128 x 32 fp32 -> split pairs ----
        {
            const float* src = A + (long)(bm + lm) * lda + k0 + kbA;
            float x[16];
            *(float4*)(x + 0)  = *(const float4*)(src + 0);
            *(float4*)(x + 4)  = *(const float4*)(src + 4);
            *(float4*)(x + 8)  = *(const float4*)(src + 8);
            *(float4*)(x + 12) = *(const float4*)(src + 12);
#pragma unroll
            for (int j = 0; j < 8; j++) {
                uint32_t hi, lo;
                split_pair(x[2 * j], x[2 * j + 1], hi, lo);
                int kp = (kbA >> 1) + j;
                As_hi[kp][lm] = hi;
                As_lo[kp][lm] = lo;
            }
        }
        // ---- load B tile ----
        if (!TB) {
            // B[k][n]: pair = two consecutive k rows
#pragma unroll
            for (int r = 0; r < 2; r++) {
                int kp = (tid >> 5) + r * 8;
                int n4 = (tid & 31) * 4;
                const float* bp = Bm + (long)(k0 + 2 * kp) * ldb + bn + n4;
                float4 r0 = *(const float4*)(bp);
                float4 r1 = *(const float4*)(bp + ldb);
                uint32_t h[4], l[4];
                split_pair(r0.x, r1.x, h[0], l[0]);
                split_pair(r0.y, r1.y, h[1], l[1]);
                split_pair(r0.z, r1.z, h[2], l[2]);
                split_pair(r0.w, r1.w, h[3], l[3]);
                *(uint4*)(&Bs_hi[kp][n4]) = make_uint4(h[0], h[1], h[2], h[3]);
                *(uint4*)(&Bs_lo[kp][n4]) = make_uint4(l[0], l[1], l[2], l[3]);
            }
        } else {
            // B[n][k]: same pattern as A
            const float* src = Bm + (long)(bn + lm) * ldb + k0 + kbA;
            float x[16];
            *(float4*)(x + 0)  = *(const float4*)(src + 0);
            *(float4*)(x + 4)  = *(const float4*)(src + 4);
            *(float4*)(x + 8)  = *(const float4*)(src + 8);
            *(float4*)(x + 12) = *(const float4*)(src + 12);
#pragma unroll
            for (int j = 0; j < 8; j++) {
                uint32_t hi, lo;
                split_pair(x[2 * j], x[2 * j + 1], hi, lo);
                int kp = (kbA >> 1) + j;
                Bs_hi[kp][lm] = hi;
                Bs_lo[kp][lm] = lo;
            }
        }
        __syncthreads();

        // ---- compute: two k16 steps ----
#pragma unroll
        for (int ks = 0; ks < 2; ks++) {
            const int kp0 = ks * 8 + t4;
            uint32_t bh0[4], bh1[4], bl0[4], bl1[4];
#pragma unroll
            for (int ct = 0; ct < 4; ct++) {
                int col = wn + ct * 8 + g;
                bh0[ct] = Bs_hi[kp0][col];
                bh1[ct] = Bs_hi[kp0 + 4][col];
                bl0[ct] = Bs_lo[kp0][col];
                bl1[ct] = Bs_lo[kp0 + 4][col];
            }
#pragma unroll
            for (int rt = 0; rt < 4; rt++) {
                int row = wm + rt * 16 + g;
                uint32_t ah0 = As_hi[kp0][row];
                uint32_t ah1 = As_hi[kp0][row + 8];
                uint32_t ah2 = As_hi[kp0 + 4][row];
                uint32_t ah3 = As_hi[kp0 + 4][row + 8];
                uint32_t al0 = As_lo[kp0][row];
                uint32_t al1 = As_lo[kp0][row + 8];
                uint32_t al2 = As_lo[kp0 + 4][row];
                uint32_t al3 = As_lo[kp0 + 4][row + 8];
#pragma unroll
                for (int ct = 0; ct < 4; ct++) {
                    mma16816(acc[rt][ct], ah0, ah1, ah2, ah3, bh0[ct], bh1[ct]);
                    mma16816(acc[rt][ct], ah0, ah1, ah2, ah3, bl0[ct], bl1[ct]);
                    mma16816(acc[rt][ct], al0, al1, al2, al3, bh0[ct], bh1[ct]);
                }
            }
        }
        __syncthreads();
    }

    // ---- epilogue ----
#pragma unroll
    for (int rt = 0; rt < 4; rt++) {
        int row0 = bm + wm + rt * 16 + g;
#pragma unroll
        for (int ct = 0; ct < 4; ct++) {
            int col0 = bn + wn + ct * 8 + 2 * t4;
            float b0 = bias ? bias[col0] : 0.f;
            float b1 = bias ? bias[col0 + 1] : 0.f;
            float2 v0 = make_float2(acc[rt][ct][0] * alpha + b0, acc[rt][ct][1] * alpha + b1);
            float2 v1 = make_float2(acc[rt][ct][2] * alpha + b0, acc[rt][ct][3] * alpha + b1);
            *(float2*)(C + (long)row0 * ldc + col0) = v0;
            *(float2*)(C + (long)(row0 + 8) * ldc + col0) = v1;
        }
    }
}

// ---------------- fused RMSNorm + RoPE -------------------------------------------
__global__ void norm_rope_kernel(float* __restrict__ x, const float* __restrict__ w,
                                 const float* __restrict__ cosT, const float* __restrict__ sinT) {
    long r = blockIdx.x;
    int h = (int)(r & 15);
    long row = r >> 4;
    int p = (int)(row & (SS - 1));
    float* ptr = x + row * 2048 + h * 128;
    int f = threadIdx.x;

    float v = ptr[f];
    float ss = v * v;
#pragma unroll
    for (int o = 16; o; o >>= 1) ss += __shfl_xor_sync(0xffffffffu, ss, o);
    __shared__ float red[4];
    if ((f & 31) == 0) red[f >> 5] = ss;
    __syncthreads();
    ss = red[0] + red[1] + red[2] + red[3];

    float rms = sqrtf(ss * (1.f / 128.f));
    float sv = v / (rms + EPSV) * w[f];

    __shared__ float sh[128];
    sh[f] = sv;
    __syncthreads();

    int i = f & 63;
    float c = cosT[p * 64 + i], s = sinT[p * 64 + i];
    float out = (f < 64) ? (sv * c - sh[f + 64] * s) : (sv * c + sh[f - 64] * s);
    ptr[f] = out;
}

// ---------------- row softmax over 2048 ------------------------------------------
__global__ __launch_bounds__(256)
void softmax_kernel(float* __restrict__ sc) {
    long row = blockIdx.x;
    float* p = sc + row * 2048;
    int t = threadIdx.x;

    float v[8];
    float m = -1e30f;
#pragma unroll
    for (int j = 0; j < 8; j++) {
        v[j] = p[t + 256 * j];
        m = fmaxf(m, v[j]);
    }
#pragma unroll
    for (int o = 16; o; o >>= 1) m = fmaxf(m, __shfl_xor_sync(0xffffffffu, m, o));
    __shared__ float redm[8];
    __shared__ float reds[8];
    if ((t & 31) == 0) redm[t >> 5] = m;
    __syncthreads();
    m = redm[0];
#pragma unroll
    for (int j = 1; j < 8; j++) m = fmaxf(m, redm[j]);

    float s = 0.f;
#pragma unroll
    for (int j = 0; j < 8; j++) {
        v[j] = expf(v[j] - m);
        s += v[j];
    }
#pragma unroll
    for (int o = 16; o; o >>= 1) s += __shfl_xor_sync(0xffffffffu, s, o);
    if ((t & 31) == 0) reds[t >> 5] = s;
    __syncthreads();
    s = reds[0];
#pragma unroll
    for (int j = 1; j < 8; j++) s += reds[j];

    float inv = 1.f / s;
#pragma unroll
    for (int j = 0; j < 8; j++) p[t + 256 * j] = v[j] * inv;
}

// ---------------- host orchestration ----------------------------------------------
extern "C" void kernel_launch(void* const* d_in, const int* in_sizes, int n_in,
                              void* d_out, int out_size) {
    const float* xq = (const float*)d_in[0];
    const float* xk = (const float*)d_in[1];
    const float* xv = (const float*)d_in[2];
    const float* WQ = (const float*)d_in[3];
    const float* WK = (const float*)d_in[4];
    const float* WV = (const float*)d_in[5];
    const float* WO = (const float*)d_in[6];
    const float* bQ = (const float*)d_in[7];
    const float* bK = (const float*)d_in[8];
    const float* bV = (const float*)d_in[9];
    const float* bO = (const float*)d_in[10];
    const float* qw = (const float*)d_in[11];
    const float* kw = (const float*)d_in[12];
    float* out = (float*)d_out;

    float *wt0, *wt1, *wt2, *qb, *kb, *vb, *ab, *sc, *ct, *st;
    cudaGetSymbolAddress((void**)&wt0, g_wt0);
    cudaGetSymbolAddress((void**)&wt1, g_wt1);
    cudaGetSymbolAddress((void**)&wt2, g_wt2);
    cudaGetSymbolAddress((void**)&qb, g_q);
    cudaGetSymbolAddress((void**)&kb, g_k);
    cudaGetSymbolAddress((void**)&vb, g_v);
    cudaGetSymbolAddress((void**)&ab, g_attn);
    cudaGetSymbolAddress((void**)&sc, g_sc);
    cudaGetSymbolAddress((void**)&ct, g_cos);
    cudaGetSymbolAddress((void**)&st, g_sin);

    const long M4 = 4194304;  // 2048*2048

    rope_table_kernel<<<(2048 * 64 + 255) / 256, 256>>>(ct, st);
    transpose_w_kernel<<<16384, 256>>>(WQ, wt0);
    transpose_w_kernel<<<16384, 256>>>(WK, wt1);
    transpose_w_kernel<<<16384, 256>>>(WV, wt2);

    // QKV projections
    dim3 gProj(16, 32, 1);
    bgemm_kernel<false><<<gProj, 256>>>(xq, wt0, qb, bQ, 4096, 2048, 2048, 2048, 2048, 2048,
                                        1, 0, 0, 1, 0, 0, 1, 0, 0, 1.f);
    bgemm_kernel<false><<<gProj, 256>>>(xk, wt1, kb, bK, 4096, 2048, 2048, 2048, 2048, 2048,
                                        1, 0, 0, 1, 0, 0, 1, 0, 0, 1.f);
    bgemm_kernel<false><<<gProj, 256>>>(xv, wt2, vb, bV, 4096, 2048, 2048, 2048, 2048, 2048,
                                        1, 0, 0, 1, 0, 0, 1, 0, 0, 1.f);

    norm_rope_kernel<<<BB * SS * HH, 128>>>(qb, qw, ct, st);
    norm_rope_kernel<<<BB * SS * HH, 128>>>(kb, kw, ct, st);

    // scores = (1/sqrt(F)) * q @ k^T  (NT, batched over 32)
    dim3 gScore(16, 16, 32);
    bgemm_kernel<true><<<gScore, 256>>>(qb, kb, sc, nullptr, 2048, 2048, 128, 2048, 2048, 2048,
                                        16, M4, 128,
                                        16, M4, 128,
                                        1, M4, 0,
                                        0.08838834764831845f);

    softmax_kernel<<<32 * 2048, 256>>>(sc);

    // attn = P @ v  (NN, batched over 32)
    dim3 gPV(1, 16, 32);
    bgemm_kernel<false><<<gPV, 256>>>(sc, vb, ab, nullptr, 2048, 128, 2048, 2048, 2048, 2048,
                                      1, M4, 0,
                                      16, M4, 128,
                                      16, M4, 128,
                                      1.f);

    // output projection
    bgemm_kernel<false><<<gProj, 256>>>(ab, WO, out, bO, 4096, 2048, 2048, 2048, 2048, 2048,
                                        1, 0, 0, 1, 0, 0, 1, 0, 0, 1.f);
}

// round 4
// speedup vs baseline: 2.2605x; 1.2165x over previous
#include <cuda_runtime.h>
#include <cuda_bf16.h>
#include <cstdint>
#include <math.h>

#define BB 2
#define SS 2048
#define DD 2048
#define HH 16
#define FF 128
#define EPSV 1e-6f

// ---------------- scratch (static device memory; no allocations) ----------------
__device__ float g_wt0[2048 * 2048];
__device__ float g_wt1[2048 * 2048];
__device__ float g_wt2[2048 * 2048];
__device__ float g_q[4096 * 2048];
__device__ float g_k[4096 * 2048];
__device__ float g_v[4096 * 2048];
__device__ float g_attn[4096 * 2048];
__device__ float g_cos[2048 * 64];
__device__ float g_sin[2048 * 64];
// pre-split bf16 pair arrays (hi/lo), pairs along F: [row 4096][pair 1024]
__device__ uint32_t g_qhi[4096 * 1024];
__device__ uint32_t g_qlo[4096 * 1024];
__device__ uint32_t g_khi[4096 * 1024];
__device__ uint32_t g_klo[4096 * 1024];
// V transposed split: [b*2048 + h*128 + f][ppair 1024]
__device__ uint32_t g_vthi[2 * 2048 * 1024];
__device__ uint32_t g_vtlo[2 * 2048 * 1024];

// ---------------- RoPE table -----------------------------------------------------
__global__ void rope_table_kernel(float* __restrict__ cosT, float* __restrict__ sinT) {
    int idx = blockIdx.x * 256 + threadIdx.x;
    if (idx >= 2048 * 64) return;
    int p = idx / 64, i = idx % 64;
    float freq = (float)(1.0 / pow(10000.0, (double)i / 64.0));
    float a = (float)p * freq;
    cosT[idx] = (float)cos((double)a);
    sinT[idx] = (float)sin((double)a);
}

// ---------------- weight transpose: W[H,D,F] -> Wt[D, H*F] -----------------------
__global__ void transpose_w_kernel(const float* __restrict__ W, float* __restrict__ Wt) {
    int idx = blockIdx.x * 256 + threadIdx.x;
    int n = idx & 2047;
    int d = idx >> 11;
    int h = n >> 7, f = n & 127;
    Wt[idx] = W[(h * 2048 + d) * 128 + f];
}

// ---------------- bf16 split helpers ---------------------------------------------
__device__ __forceinline__ uint32_t pack2(__nv_bfloat16 a, __nv_bfloat16 b) {
    __nv_bfloat162 h2;
    h2.x = a; h2.y = b;
    return *reinterpret_cast<uint32_t*>(&h2);
}

__device__ __forceinline__ void split_pair(float e0, float e1, uint32_t& hi, uint32_t& lo) {
    __nv_bfloat16 h0 = __float2bfloat16_rn(e0);
    __nv_bfloat16 h1 = __float2bfloat16_rn(e1);
    float l0 = e0 - __bfloat162float(h0);
    float l1 = e1 - __bfloat162float(h1);
    hi = pack2(h0, h1);
    lo = pack2(__float2bfloat16_rn(l0), __float2bfloat16_rn(l1));
}

__device__ __forceinline__ void mma16816(float* c, uint32_t a0, uint32_t a1, uint32_t a2,
                                         uint32_t a3, uint32_t b0, uint32_t b1) {
    asm volatile(
        "mma.sync.aligned.m16n8k16.row.col.f32.bf16.bf16.f32 "
        "{%0,%1,%2,%3},{%4,%5,%6,%7},{%8,%9},{%0,%1,%2,%3};\n"
        : "+f"(c[0]), "+f"(c[1]), "+f"(c[2]), "+f"(c[3])
        : "r"(a0), "r"(a1), "r"(a2), "r"(a3), "r"(b0), "r"(b1));
}

__device__ __forceinline__ void cpa16(uint32_t dst, const void* src) {
    asm volatile("cp.async.cg.shared.global [%0], [%1], 16;\n" :: "r"(dst), "l"(src));
}

// ---------------- split-bf16 tensor-core GEMM (NN/NT), batched, fused bias -------
#define LDS_W 136
template <bool TB>
__global__ __launch_bounds__(256, 2)
void bgemm_kernel(const float* __restrict__ A, const float* __restrict__ Bm,
                  float* __restrict__ C, const float* __restrict__ bias,
                  int M, int N, int K, int lda, int ldb, int ldc,
                  int zdivA, long sA1, long sA2,
                  int zdivB, long sB1, long sB2,
                  int zdivC, long sC1, long sC2,
                  float alpha) {
    int z = blockIdx.z;
    A += (long)(z / zdivA) * sA1 + (long)(z % zdivA) * sA2;
    Bm += (long)(z / zdivB) * sB1 + (long)(z % zdivB) * sB2;
    C += (long)(z / zdivC) * sC1 + (long)(z % zdivC) * sC2;

    __shared__ uint32_t As_hi[16][LDS_W];
    __shared__ uint32_t As_lo[16][LDS_W];
    __shared__ uint32_t Bs_hi[16][LDS_W];
    __shared__ uint32_t Bs_lo[16][LDS_W];

    const int tid = threadIdx.x;
    const int lane = tid & 31;
    const int warp = tid >> 5;
    const int wm = (warp >> 2) * 64;
    const int wn = (warp & 3) * 32;
    const int g = lane >> 2;
    const int t4 = lane & 3;
    const int bm = blockIdx.y * 128, bn = blockIdx.x * 128;

    const int lm = tid & 127;
    const int kbA = (tid >> 7) * 16;

    float acc[4][4][4];
#pragma unroll
    for (int i = 0; i < 4; i++)
#pragma unroll
        for (int j = 0; j < 4; j++)
#pragma unroll
            for (int r = 0; r < 4; r++) acc[i][j][r] = 0.f;

    for (int k0 = 0; k0 < K; k0 += 32) {
        {
            const float* src = A + (long)(bm + lm) * lda + k0 + kbA;
            float x[16];
            *(float4*)(x + 0)  = *(const float4*)(src + 0);
            *(float4*)(x + 4)  = *(const float4*)(src + 4);
            *(float4*)(x + 8)  = *(const float4*)(src + 8);
            *(float4*)(x + 12) = *(const float4*)(src + 12);
#pragma unroll
            for (int j = 0; j < 8; j++) {
                uint32_t hi, lo;
                split_pair(x[2 * j], x[2 * j + 1], hi, lo);
                int kp = (kbA >> 1) + j;
                As_hi[kp][lm] = hi;
                As_lo[kp][lm] = lo;
            }
        }
        if (!TB) {
#pragma unroll
            for (int r = 0; r < 2; r++) {
                int kp = (tid >> 5) + r * 8;
                int n4 = (tid & 31) * 4;
                const float* bp = Bm + (long)(k0 + 2 * kp) * ldb + bn + n4;
                float4 r0 = *(const float4*)(bp);
                float4 r1 = *(const float4*)(bp + ldb);
                uint32_t h[4], l[4];
                split_pair(r0.x, r1.x, h[0], l[0]);
                split_pair(r0.y, r1.y, h[1], l[1]);
                split_pair(r0.z, r1.z, h[2], l[2]);
                split_pair(r0.w, r1.w, h[3], l[3]);
                *(uint4*)(&Bs_hi[kp][n4]) = make_uint4(h[0], h[1], h[2], h[3]);
                *(uint4*)(&Bs_lo[kp][n4]) = make_uint4(l[0], l[1], l[2], l[3]);
            }
        } else {
            const float* src = Bm + (long)(bn + lm) * ldb + k0 + kbA;
            float x[16];
            *(float4*)(x + 0)  = *(const float4*)(src + 0);
            *(float4*)(x + 4)  = *(const float4*)(src + 4);
            *(float4*)(x + 8)  = *(const float4*)(src + 8);
            *(float4*)(x + 12) = *(const float4*)(src + 12);
#pragma unroll
            for (int j = 0; j < 8; j++) {
                uint32_t hi, lo;
                split_pair(x[2 * j], x[2 * j + 1], hi, lo);
                int kp = (kbA >> 1) + j;
                Bs_hi[kp][lm] = hi;
                Bs_lo[kp][lm] = lo;
            }
        }
        __syncthreads();

#pragma unroll
        for (int ks = 0; ks < 2; ks++) {
            const int kp0 = ks * 8 + t4;
            uint32_t bh0[4], bh1[4], bl0[4], bl1[4];
#pragma unroll
            for (int ct = 0; ct < 4; ct++) {
                int col = wn + ct * 8 + g;
                bh0[ct] = Bs_hi[kp0][col];
                bh1[ct] = Bs_hi[kp0 + 4][col];
                bl0[ct] = Bs_lo[kp0][col];
                bl1[ct] = Bs_lo[kp0 + 4][col];
            }
#pragma unroll
            for (int rt = 0; rt < 4; rt++) {
                int row = wm + rt * 16 + g;
                uint32_t ah0 = As_hi[kp0][row];
                uint32_t ah1 = As_hi[kp0][row + 8];
                uint32_t ah2 = As_hi[kp0 + 4][row];
                uint32_t ah3 = As_hi[kp0 + 4][row + 8];
                uint32_t al0 = As_lo[kp0][row];
                uint32_t al1 = As_lo[kp0][row + 8];
                uint32_t al2 = As_lo[kp0 + 4][row];
                uint32_t al3 = As_lo[kp0 + 4][row + 8];
#pragma unroll
                for (int ct = 0; ct < 4; ct++) {
                    mma16816(acc[rt][ct], ah0, ah1, ah2, ah3, bh0[ct], bh1[ct]);
                    mma16816(acc[rt][ct], ah0, ah1, ah2, ah3, bl0[ct], bl1[ct]);
                    mma16816(acc[rt][ct], al0, al1, al2, al3, bh0[ct], bh1[ct]);
                }
            }
        }
        __syncthreads();
    }

#pragma unroll
    for (int rt = 0; rt < 4; rt++) {
        int row0 = bm + wm + rt * 16 + g;
#pragma unroll
        for (int ct = 0; ct < 4; ct++) {
            int col0 = bn + wn + ct * 8 + 2 * t4;
            float b0 = bias ? bias[col0] : 0.f;
            float b1 = bias ? bias[col0 + 1] : 0.f;
            float2 v0 = make_float2(acc[rt][ct][0] * alpha + b0, acc[rt][ct][1] * alpha + b1);
            float2 v1 = make_float2(acc[rt][ct][2] * alpha + b0, acc[rt][ct][3] * alpha + b1);
            *(float2*)(C + (long)row0 * ldc + col0) = v0;
            *(float2*)(C + (long)(row0 + 8) * ldc + col0) = v1;
        }
    }
}

// ---------------- fused RMSNorm + RoPE -> split bf16 pair arrays ------------------
__global__ void norm_rope_split_kernel(const float* __restrict__ x, const float* __restrict__ w,
                                       const float* __restrict__ cosT, const float* __restrict__ sinT,
                                       uint32_t* __restrict__ ohi, uint32_t* __restrict__ olo,
                                       float scale) {
    long r = blockIdx.x;
    int h = (int)(r & 15);
    long row = r >> 4;
    int p = (int)(row & (SS - 1));
    const float* ptr = x + row * 2048 + h * 128;
    int f = threadIdx.x;

    float v = ptr[f];
    float ss = v * v;
#pragma unroll
    for (int o = 16; o; o >>= 1) ss += __shfl_xor_sync(0xffffffffu, ss, o);
    __shared__ float red[4];
    if ((f & 31) == 0) red[f >> 5] = ss;
    __syncthreads();
    ss = red[0] + red[1] + red[2] + red[3];

    float rms = sqrtf(ss * (1.f / 128.f));
    float sv = v / (rms + EPSV) * w[f];

    __shared__ float sh[128];
    __shared__ float sh2[128];
    sh[f] = sv;
    __syncthreads();

    int i = f & 63;
    float c = cosT[p * 64 + i], s = sinT[p * 64 + i];
    float out = (f < 64) ? (sv * c - sh[f + 64] * s) : (sv * c + sh[f - 64] * s);
    sh2[f] = out * scale;
    __syncthreads();

    if (f < 64) {
        uint32_t hi, lo;
        split_pair(sh2[2 * f], sh2[2 * f + 1], hi, lo);
        long o = row * 1024 + h * 64 + f;
        ohi[o] = hi;
        olo[o] = lo;
    }
}

// ---------------- V transpose + split: v[4096][2048] -> vt[col][ppair] -----------
__global__ void v_tsplit_kernel(const float* __restrict__ v,
                                uint32_t* __restrict__ vthi, uint32_t* __restrict__ vtlo) {
    int b = blockIdx.z, pb = blockIdx.y, cb = blockIdx.x;   // tile 64p x 64c
    __shared__ float ts[64][65];
    int tid = threadIdx.x;
#pragma unroll
    for (int i = 0; i < 16; i++) {
        int idx = i * 256 + tid;
        int r = idx >> 6, c = idx & 63;
        ts[r][c] = v[(long)(b * 2048 + pb * 64 + r) * 2048 + cb * 64 + c];
    }
    __syncthreads();
#pragma unroll
    for (int i = 0; i < 8; i++) {
        int idx = i * 256 + tid;           // 0..2047
        int c = idx >> 5, pp = idx & 31;
        uint32_t hi, lo;
        split_pair(ts[2 * pp][c], ts[2 * pp + 1][c], hi, lo);
        long dst = (long)(b * 2048 + cb * 64 + c) * 1024 + pb * 32 + pp;
        vthi[dst] = hi;
        vtlo[dst] = lo;
    }
}

// ---------------- flash attention -------------------------------------------------
// grid (16 q-tiles, 32 bh); 256 threads; q-tile 128 rows, kv-tile 64 rows.
#define FL_KSLO 17408
#define FL_VSHI 34816
#define FL_VSLO 53248
#define FL_STAGE 71680
#define FL_SMEM  143360

__global__ __launch_bounds__(256, 1)
void flash_kernel(const uint32_t* __restrict__ qhi, const uint32_t* __restrict__ qlo,
                  const uint32_t* __restrict__ khi, const uint32_t* __restrict__ klo,
                  const uint32_t* __restrict__ vthi, const uint32_t* __restrict__ vtlo,
                  float* __restrict__ attn) {
    extern __shared__ char fsm[];
    const int tid = threadIdx.x;
    const int lane = tid & 31, warp = tid >> 5;
    const int g = lane >> 2, t4 = lane & 3;
    const int qt = blockIdx.x, bh = blockIdx.y;
    const int b = bh >> 4, h = bh & 15;
    const int wm = warp * 16;
    const long qr0 = (long)b * 2048 + qt * 128;

    const uint32_t smem_base = (uint32_t)__cvta_generic_to_shared(fsm);

    // ---- Q fragments (registers), pairs along F ----
    uint32_t qah[8][4], qal[8][4];
    {
        const uint32_t* qh0 = qhi + (qr0 + wm + g) * 1024 + h * 64;
        const uint32_t* qh8 = qhi + (qr0 + wm + g + 8) * 1024 + h * 64;
        const uint32_t* ql0 = qlo + (qr0 + wm + g) * 1024 + h * 64;
        const uint32_t* ql8 = qlo + (qr0 + wm + g + 8) * 1024 + h * 64;
#pragma unroll
        for (int fs = 0; fs < 8; fs++) {
            qah[fs][0] = qh0[8 * fs + t4];
            qah[fs][1] = qh8[8 * fs + t4];
            qah[fs][2] = qh0[8 * fs + 4 + t4];
            qah[fs][3] = qh8[8 * fs + 4 + t4];
            qal[fs][0] = ql0[8 * fs + t4];
            qal[fs][1] = ql8[8 * fs + t4];
            qal[fs][2] = ql0[8 * fs + 4 + t4];
            qal[fs][3] = ql8[8 * fs + 4 + t4];
        }
    }

    float acc_o[16][4];
#pragma unroll
    for (int nt = 0; nt < 16; nt++)
#pragma unroll
        for (int j = 0; j < 4; j++) acc_o[nt][j] = 0.f;
    float mrow[2] = {-1e30f, -1e30f};
    float lrow[2] = {0.f, 0.f};

    const uint32_t* khb = khi + ((long)b * 2048) * 1024 + h * 64;
    const uint32_t* klb = klo + ((long)b * 2048) * 1024 + h * 64;
    const uint32_t* vhb = vthi + ((long)b * 2048 + h * 128) * 1024;
    const uint32_t* vlb = vtlo + ((long)b * 2048 + h * 128) * 1024;

    // prefetch macro-ish lambda
    auto prefetch = [&](int kb) {
        uint32_t sb = smem_base + (kb & 1) * FL_STAGE;
        const uint32_t* kh = khb + (long)kb * 64 * 1024;
        const uint32_t* kl = klb + (long)kb * 64 * 1024;
#pragma unroll
        for (int i = 0; i < 4; i++) {
            int c = tid + i * 256;
            int row = c >> 4, cc = (c & 15) * 4;
            cpa16(sb + (row * 68 + cc) * 4, kh + (long)row * 1024 + cc);
            cpa16(sb + FL_KSLO + (row * 68 + cc) * 4, kl + (long)row * 1024 + cc);
        }
#pragma unroll
        for (int i = 0; i < 4; i++) {
            int c = tid + i * 256;
            int col = c >> 3, ci = (c & 7) * 4;
            cpa16(sb + FL_VSHI + (col * 36 + ci) * 4, vhb + (long)col * 1024 + kb * 32 + ci);
            cpa16(sb + FL_VSLO + (col * 36 + ci) * 4, vlb + (long)col * 1024 + kb * 32 + ci);
        }
        asm volatile("cp.async.commit_group;\n" ::: "memory");
    };

    prefetch(0);

    for (int kb = 0; kb < 32; kb++) {
        if (kb + 1 < 32) {
            prefetch(kb + 1);
            asm volatile("cp.async.wait_group 1;\n" ::: "memory");
        } else {
            asm volatile("cp.async.wait_group 0;\n" ::: "memory");
        }
        __syncthreads();

        const uint32_t* ksh = (const uint32_t*)(fsm + (kb & 1) * FL_STAGE);
        const uint32_t* ksl = (const uint32_t*)(fsm + (kb & 1) * FL_STAGE + FL_KSLO);
        const uint32_t* vsh = (const uint32_t*)(fsm + (kb & 1) * FL_STAGE + FL_VSHI);
        const uint32_t* vsl = (const uint32_t*)(fsm + (kb & 1) * FL_STAGE + FL_VSLO);

        // ---- S = Q @ K^T (128 x 64), 3-pass split ----
        float sacc[8][4];
#pragma unroll
        for (int nt = 0; nt < 8; nt++)
#pragma unroll
            for (int j = 0; j < 4; j++) sacc[nt][j] = 0.f;

#pragma unroll
        for (int fs = 0; fs < 8; fs++) {
            uint32_t kb0h[8], kb1h[8], kb0l[8], kb1l[8];
#pragma unroll
            for (int nt = 0; nt < 8; nt++) {
                int o = (nt * 8 + g) * 68 + fs * 8 + t4;
                kb0h[nt] = ksh[o];
                kb1h[nt] = ksh[o + 4];
                kb0l[nt] = ksl[o];
                kb1l[nt] = ksl[o + 4];
            }
#pragma unroll
            for (int nt = 0; nt < 8; nt++) {
                mma16816(sacc[nt], qah[fs][0], qah[fs][1], qah[fs][2], qah[fs][3], kb0h[nt], kb1h[nt]);
                mma16816(sacc[nt], qah[fs][0], qah[fs][1], qah[fs][2], qah[fs][3], kb0l[nt], kb1l[nt]);
                mma16816(sacc[nt], qal[fs][0], qal[fs][1], qal[fs][2], qal[fs][3], kb0h[nt], kb1h[nt]);
            }
        }

        // ---- online softmax (rows g, g+8) ----
#pragma unroll
        for (int r = 0; r < 2; r++) {
            float m_ = -1e30f;
#pragma unroll
            for (int nt = 0; nt < 8; nt++)
                m_ = fmaxf(m_, fmaxf(sacc[nt][2 * r], sacc[nt][2 * r + 1]));
            m_ = fmaxf(m_, __shfl_xor_sync(0xffffffffu, m_, 1));
            m_ = fmaxf(m_, __shfl_xor_sync(0xffffffffu, m_, 2));

            float mnew = fmaxf(mrow[r], m_);
            float scale = __expf(mrow[r] - mnew);
            mrow[r] = mnew;

            float rs = 0.f;
#pragma unroll
            for (int nt = 0; nt < 8; nt++) {
                float p0 = __expf(sacc[nt][2 * r] - mnew);
                float p1 = __expf(sacc[nt][2 * r + 1] - mnew);
                sacc[nt][2 * r] = p0;
                sacc[nt][2 * r + 1] = p1;
                rs += p0 + p1;
            }
            rs += __shfl_xor_sync(0xffffffffu, rs, 1);
            rs += __shfl_xor_sync(0xffffffffu, rs, 2);
            lrow[r] = lrow[r] * scale + rs;
#pragma unroll
            for (int nt = 0; nt < 16; nt++) {
                acc_o[nt][2 * r] *= scale;
                acc_o[nt][2 * r + 1] *= scale;
            }
        }

        // ---- O += P @ V (128 x 128), 3-pass split; P frags from sacc ----
#pragma unroll
        for (int s = 0; s < 4; s++) {
            uint32_t ph[4], pl[4];
            {
                uint32_t h0, l0;
                split_pair(sacc[2 * s][0], sacc[2 * s][1], h0, l0);         ph[0] = h0; pl[0] = l0;
                split_pair(sacc[2 * s][2], sacc[2 * s][3], h0, l0);         ph[1] = h0; pl[1] = l0;
                split_pair(sacc[2 * s + 1][0], sacc[2 * s + 1][1], h0, l0); ph[2] = h0; pl[2] = l0;
                split_pair(sacc[2 * s + 1][2], sacc[2 * s + 1][3], h0, l0); ph[3] = h0; pl[3] = l0;
            }
#pragma unroll
            for (int nt = 0; nt < 16; nt++) {
                int o = (nt * 8 + g) * 36 + s * 8 + t4;
                uint32_t v0h = vsh[o], v1h = vsh[o + 4];
                uint32_t v0l = vsl[o], v1l = vsl[o + 4];
                mma16816(acc_o[nt], ph[0], ph[1], ph[2], ph[3], v0h, v1h);
                mma16816(acc_o[nt], pl[0], pl[1], pl[2], pl[3], v0h, v1h);
                mma16816(acc_o[nt], ph[0], ph[1], ph[2], ph[3], v0l, v1l);
            }
        }
        __syncthreads();
    }

    // ---- epilogue: normalize and store ----
    float inv0 = 1.f / lrow[0];
    float inv1 = 1.f / lrow[1];
    float* o0 = attn + (qr0 + wm + g) * 2048 + h * 128;
    float* o8 = attn + (qr0 + wm + g + 8) * 2048 + h * 128;
#pragma unroll
    for (int nt = 0; nt < 16; nt++) {
        int col = nt * 8 + 2 * t4;
        *(float2*)(o0 + col) = make_float2(acc_o[nt][0] * inv0, acc_o[nt][1] * inv0);
        *(float2*)(o8 + col) = make_float2(acc_o[nt][2] * inv1, acc_o[nt][3] * inv1);
    }
}

// ---------------- host orchestration ----------------------------------------------
extern "C" void kernel_launch(void* const* d_in, const int* in_sizes, int n_in,
                              void* d_out, int out_size) {
    const float* xq = (const float*)d_in[0];
    const float* xk = (const float*)d_in[1];
    const float* xv = (const float*)d_in[2];
    const float* WQ = (const float*)d_in[3];
    const float* WK = (const float*)d_in[4];
    const float* WV = (const float*)d_in[5];
    const float* WO = (const float*)d_in[6];
    const float* bQ = (const float*)d_in[7];
    const float* bK = (const float*)d_in[8];
    const float* bV = (const float*)d_in[9];
    const float* bO = (const float*)d_in[10];
    const float* qw = (const float*)d_in[11];
    const float* kw = (const float*)d_in[12];
    float* out = (float*)d_out;

    float *wt0, *wt1, *wt2, *qb, *kb, *vb, *ab, *ct, *st;
    uint32_t *qhi, *qlo, *khi, *klo, *vthi, *vtlo;
    cudaGetSymbolAddress((void**)&wt0, g_wt0);
    cudaGetSymbolAddress((void**)&wt1, g_wt1);
    cudaGetSymbolAddress((void**)&wt2, g_wt2);
    cudaGetSymbolAddress((void**)&qb, g_q);
    cudaGetSymbolAddress((void**)&kb, g_k);
    cudaGetSymbolAddress((void**)&vb, g_v);
    cudaGetSymbolAddress((void**)&ab, g_attn);
    cudaGetSymbolAddress((void**)&ct, g_cos);
    cudaGetSymbolAddress((void**)&st, g_sin);
    cudaGetSymbolAddress((void**)&qhi, g_qhi);
    cudaGetSymbolAddress((void**)&qlo, g_qlo);
    cudaGetSymbolAddress((void**)&khi, g_khi);
    cudaGetSymbolAddress((void**)&klo, g_klo);
    cudaGetSymbolAddress((void**)&vthi, g_vthi);
    cudaGetSymbolAddress((void**)&vtlo, g_vtlo);

    cudaFuncSetAttribute(flash_kernel, cudaFuncAttributeMaxDynamicSharedMemorySize, FL_SMEM);

    rope_table_kernel<<<(2048 * 64 + 255) / 256, 256>>>(ct, st);
    transpose_w_kernel<<<16384, 256>>>(WQ, wt0);
    transpose_w_kernel<<<16384, 256>>>(WK, wt1);
    transpose_w_kernel<<<16384, 256>>>(WV, wt2);

    // QKV projections
    dim3 gProj(16, 32, 1);
    bgemm_kernel<false><<<gProj, 256>>>(xq, wt0, qb, bQ, 4096, 2048, 2048, 2048, 2048, 2048,
                                        1, 0, 0, 1, 0, 0, 1, 0, 0, 1.f);
    bgemm_kernel<false><<<gProj, 256>>>(xk, wt1, kb, bK, 4096, 2048, 2048, 2048, 2048, 2048,
                                        1, 0, 0, 1, 0, 0, 1, 0, 0, 1.f);
    bgemm_kernel<false><<<gProj, 256>>>(xv, wt2, vb, bV, 4096, 2048, 2048, 2048, 2048, 2048,
                                        1, 0, 0, 1, 0, 0, 1, 0, 0, 1.f);

    // RMSNorm + RoPE + split (q scaled by 1/sqrt(F))
    norm_rope_split_kernel<<<BB * SS * HH, 128>>>(qb, qw, ct, st, qhi, qlo, 0.08838834764831845f);
    norm_rope_split_kernel<<<BB * SS * HH, 128>>>(kb, kw, ct, st, khi, klo, 1.f);

    // V transpose + split
    dim3 gV(32, 32, 2);
    v_tsplit_kernel<<<gV, 256>>>(vb, vthi, vtlo);

    // flash attention -> g_attn
    dim3 gF(16, 32);
    flash_kernel<<<gF, 256, FL_SMEM>>>(qhi, qlo, khi, klo, vthi, vtlo, ab);

    // output projection
    bgemm_kernel<false><<<gProj, 256>>>(ab, WO, out, bO, 4096, 2048, 2048, 2048, 2048, 2048,
                                        1, 0, 0, 1, 0, 0, 1, 0, 0, 1.f);
}

// round 5
// speedup vs baseline: 2.8952x; 1.2808x over previous
#include <cuda_runtime.h>
#include <cuda_bf16.h>
#include <cstdint>
#include <math.h>

#define BB 2
#define SS 2048
#define DD 2048
#define HH 16
#define FF 128
#define EPSV 1e-6f

// ---------------- scratch (static device memory; no allocations) ----------------
__device__ float g_q[4096 * 2048];
__device__ float g_k[4096 * 2048];
__device__ float g_v[4096 * 2048];
__device__ float g_cos[2048 * 64];
__device__ float g_sin[2048 * 64];
// x inputs pre-split: [row 4096][kpair 1024]
__device__ uint32_t g_xqhi[4096 * 1024];
__device__ uint32_t g_xqlo[4096 * 1024];
__device__ uint32_t g_xkhi[4096 * 1024];
__device__ uint32_t g_xklo[4096 * 1024];
__device__ uint32_t g_xvhi[4096 * 1024];
__device__ uint32_t g_xvlo[4096 * 1024];
// transposed+split weights: [kpair 1024][n 2048]
__device__ uint32_t g_w0hi[1024 * 2048];
__device__ uint32_t g_w0lo[1024 * 2048];
__device__ uint32_t g_w1hi[1024 * 2048];
__device__ uint32_t g_w1lo[1024 * 2048];
__device__ uint32_t g_w2hi[1024 * 2048];
__device__ uint32_t g_w2lo[1024 * 2048];
__device__ uint32_t g_wohi[1024 * 2048];
__device__ uint32_t g_wolo[1024 * 2048];
// normed q/k split pairs: [row 4096][pair 1024]
__device__ uint32_t g_qhi[4096 * 1024];
__device__ uint32_t g_qlo[4096 * 1024];
__device__ uint32_t g_khi[4096 * 1024];
__device__ uint32_t g_klo[4096 * 1024];
// V transposed split: [b*2048 + h*128 + f][ppair 1024]
__device__ uint32_t g_vthi[2 * 2048 * 1024];
__device__ uint32_t g_vtlo[2 * 2048 * 1024];
// attention output split pairs: [row 4096][hf-pair 1024]
__device__ uint32_t g_ahi[4096 * 1024];
__device__ uint32_t g_alo[4096 * 1024];

// ---------------- helpers ---------------------------------------------------------
__device__ __forceinline__ uint32_t pack2(__nv_bfloat16 a, __nv_bfloat16 b) {
    __nv_bfloat162 h2;
    h2.x = a; h2.y = b;
    return *reinterpret_cast<uint32_t*>(&h2);
}

__device__ __forceinline__ void split_pair(float e0, float e1, uint32_t& hi, uint32_t& lo) {
    __nv_bfloat16 h0 = __float2bfloat16_rn(e0);
    __nv_bfloat16 h1 = __float2bfloat16_rn(e1);
    float l0 = e0 - __bfloat162float(h0);
    float l1 = e1 - __bfloat162float(h1);
    hi = pack2(h0, h1);
    lo = pack2(__float2bfloat16_rn(l0), __float2bfloat16_rn(l1));
}

__device__ __forceinline__ void mma16816(float* c, uint32_t a0, uint32_t a1, uint32_t a2,
                                         uint32_t a3, uint32_t b0, uint32_t b1) {
    asm volatile(
        "mma.sync.aligned.m16n8k16.row.col.f32.bf16.bf16.f32 "
        "{%0,%1,%2,%3},{%4,%5,%6,%7},{%8,%9},{%0,%1,%2,%3};\n"
        : "+f"(c[0]), "+f"(c[1]), "+f"(c[2]), "+f"(c[3])
        : "r"(a0), "r"(a1), "r"(a2), "r"(a3), "r"(b0), "r"(b1));
}

__device__ __forceinline__ void cpa16(uint32_t dst, const void* src) {
    asm volatile("cp.async.cg.shared.global [%0], [%1], 16;\n" :: "r"(dst), "l"(src));
}

// ---------------- RoPE table -----------------------------------------------------
__global__ void rope_table_kernel(float* __restrict__ cosT, float* __restrict__ sinT) {
    int idx = blockIdx.x * 256 + threadIdx.x;
    if (idx >= 2048 * 64) return;
    int p = idx / 64, i = idx % 64;
    float freq = (float)(1.0 / pow(10000.0, (double)i / 64.0));
    float a = (float)p * freq;
    cosT[idx] = (float)cos((double)a);
    sinT[idx] = (float)sin((double)a);
}

// ---------------- pre-split kernels ----------------------------------------------
// x[4096][2048] fp32 -> pairs [row][1024]
__global__ void split_rows_kernel(const float* __restrict__ x,
                                  uint32_t* __restrict__ xhi, uint32_t* __restrict__ xlo) {
    int idx = blockIdx.x * 256 + threadIdx.x;   // over 4096*1024
    float2 v = ((const float2*)x)[idx];
    uint32_t hi, lo;
    split_pair(v.x, v.y, hi, lo);
    xhi[idx] = hi;
    xlo[idx] = lo;
}

// W[h,d,f] -> pairs over d: [kp=d/2][n=h*128+f]
__global__ void wsplit_kernel(const float* __restrict__ W,
                              uint32_t* __restrict__ whi, uint32_t* __restrict__ wlo) {
    int idx = blockIdx.x * 256 + threadIdx.x;   // over 1024*2048
    int kp = idx >> 11, n = idx & 2047;
    int h = n >> 7, f = n & 127;
    float a = W[((long)h * 2048 + 2 * kp) * 128 + f];
    float b = W[((long)h * 2048 + 2 * kp + 1) * 128 + f];
    uint32_t hi, lo;
    split_pair(a, b, hi, lo);
    whi[idx] = hi;
    wlo[idx] = lo;
}

// WO[hf][m] -> pairs over hf: [kp=hf/2][m]
__global__ void wosplit_kernel(const float* __restrict__ WO,
                               uint32_t* __restrict__ whi, uint32_t* __restrict__ wlo) {
    int idx = blockIdx.x * 256 + threadIdx.x;   // over 1024*2048
    int kp = idx >> 11, m = idx & 2047;
    float a = WO[(long)(2 * kp) * 2048 + m];
    float b = WO[(long)(2 * kp + 1) * 2048 + m];
    uint32_t hi, lo;
    split_pair(a, b, hi, lo);
    whi[idx] = hi;
    wlo[idx] = lo;
}

// ---------------- pipelined split-bf16 GEMM on pre-split pair arrays -------------
// C[M,N] = A(pairs)[M][K/2] @ B(pairs)[K/2][N] + bias. M=4096,N=2048,K=2048.
// 128x128 tile, kc=32 (16 pairs), 2-stage cp.async pipeline, 8 warps.
#define G2_AS_LO 10240
#define G2_BS_HI 20480
#define G2_BS_LO 29184
#define G2_STAGE 37888
#define G2_SMEM  75776

__global__ __launch_bounds__(256, 2)
void bgemm2_kernel(const uint32_t* __restrict__ Ahi, const uint32_t* __restrict__ Alo,
                   const uint32_t* __restrict__ Bhi, const uint32_t* __restrict__ Blo,
                   float* __restrict__ C, const float* __restrict__ bias,
                   int M, int N, int K) {
    extern __shared__ char gsm[];
    const uint32_t smem_base = (uint32_t)__cvta_generic_to_shared(gsm);
    const int ldap = K >> 1;   // pairs per A row
    const int ldbp = N;

    const int tid = threadIdx.x;
    const int lane = tid & 31;
    const int warp = tid >> 5;
    const int wm = (warp >> 2) * 64;
    const int wn = (warp & 3) * 32;
    const int g = lane >> 2;
    const int t4 = lane & 3;
    const int bm = blockIdx.y * 128, bn = blockIdx.x * 128;
    const int T = K / 32;

    float acc[4][4][4];
#pragma unroll
    for (int i = 0; i < 4; i++)
#pragma unroll
        for (int j = 0; j < 4; j++)
#pragma unroll
            for (int r = 0; r < 4; r++) acc[i][j][r] = 0.f;

    auto prefetch = [&](int t) {
        uint32_t sb = smem_base + (t & 1) * G2_STAGE;
        // A: 128 rows x 16 pairs (hi+lo): 512 16B-chunks each
#pragma unroll
        for (int i = 0; i < 2; i++) {
            int c = tid + i * 256;
            int row = c >> 2, q4 = (c & 3) * 4;
            const uint32_t* sh = Ahi + (long)(bm + row) * ldap + t * 16 + q4;
            const uint32_t* sl = Alo + (long)(bm + row) * ldap + t * 16 + q4;
            cpa16(sb + (row * 20 + q4) * 4, sh);
            cpa16(sb + G2_AS_LO + (row * 20 + q4) * 4, sl);
        }
        // B: 16 kp x 128 cols (hi+lo)
#pragma unroll
        for (int i = 0; i < 2; i++) {
            int c = tid + i * 256;
            int kp = c >> 5, n4 = (c & 31) * 4;
            const uint32_t* sh = Bhi + (long)(t * 16 + kp) * ldbp + bn + n4;
            const uint32_t* sl = Blo + (long)(t * 16 + kp) * ldbp + bn + n4;
            cpa16(sb + G2_BS_HI + (kp * 136 + n4) * 4, sh);
            cpa16(sb + G2_BS_LO + (kp * 136 + n4) * 4, sl);
        }
        asm volatile("cp.async.commit_group;\n" ::: "memory");
    };

    prefetch(0);

    for (int t = 0; t < T; t++) {
        if (t + 1 < T) {
            prefetch(t + 1);
            asm volatile("cp.async.wait_group 1;\n" ::: "memory");
        } else {
            asm volatile("cp.async.wait_group 0;\n" ::: "memory");
        }
        __syncthreads();

        const uint32_t* ash = (const uint32_t*)(gsm + (t & 1) * G2_STAGE);
        const uint32_t* asl = (const uint32_t*)(gsm + (t & 1) * G2_STAGE + G2_AS_LO);
        const uint32_t* bsh = (const uint32_t*)(gsm + (t & 1) * G2_STAGE + G2_BS_HI);
        const uint32_t* bsl = (const uint32_t*)(gsm + (t & 1) * G2_STAGE + G2_BS_LO);

#pragma unroll
        for (int ks = 0; ks < 2; ks++) {
            const int kp0 = ks * 8 + t4;
            uint32_t bh0[4], bh1[4], bl0[4], bl1[4];
#pragma unroll
            for (int ct = 0; ct < 4; ct++) {
                int col = wn + ct * 8 + g;
                bh0[ct] = bsh[kp0 * 136 + col];
                bh1[ct] = bsh[(kp0 + 4) * 136 + col];
                bl0[ct] = bsl[kp0 * 136 + col];
                bl1[ct] = bsl[(kp0 + 4) * 136 + col];
            }
#pragma unroll
            for (int rt = 0; rt < 4; rt++) {
                int row = wm + rt * 16 + g;
                uint32_t ah0 = ash[row * 20 + kp0];
                uint32_t ah1 = ash[(row + 8) * 20 + kp0];
                uint32_t ah2 = ash[row * 20 + kp0 + 4];
                uint32_t ah3 = ash[(row + 8) * 20 + kp0 + 4];
                uint32_t al0 = asl[row * 20 + kp0];
                uint32_t al1 = asl[(row + 8) * 20 + kp0];
                uint32_t al2 = asl[row * 20 + kp0 + 4];
                uint32_t al3 = asl[(row + 8) * 20 + kp0 + 4];
#pragma unroll
                for (int ct = 0; ct < 4; ct++) {
                    mma16816(acc[rt][ct], ah0, ah1, ah2, ah3, bh0[ct], bh1[ct]);
                    mma16816(acc[rt][ct], ah0, ah1, ah2, ah3, bl0[ct], bl1[ct]);
                    mma16816(acc[rt][ct], al0, al1, al2, al3, bh0[ct], bh1[ct]);
                }
            }
        }
        __syncthreads();
    }

#pragma unroll
    for (int rt = 0; rt < 4; rt++) {
        int row0 = bm + wm + rt * 16 + g;
#pragma unroll
        for (int ct = 0; ct < 4; ct++) {
            int col0 = bn + wn + ct * 8 + 2 * t4;
            float b0 = bias ? bias[col0] : 0.f;
            float b1 = bias ? bias[col0 + 1] : 0.f;
            float2 v0 = make_float2(acc[rt][ct][0] + b0, acc[rt][ct][1] + b1);
            float2 v1 = make_float2(acc[rt][ct][2] + b0, acc[rt][ct][3] + b1);
            *(float2*)(C + (long)row0 * 2048 + col0) = v0;
            *(float2*)(C + (long)(row0 + 8) * 2048 + col0) = v1;
        }
    }
}

// ---------------- fused RMSNorm + RoPE -> split bf16 pair arrays ------------------
__global__ void norm_rope_split_kernel(const float* __restrict__ x, const float* __restrict__ w,
                                       const float* __restrict__ cosT, const float* __restrict__ sinT,
                                       uint32_t* __restrict__ ohi, uint32_t* __restrict__ olo,
                                       float scale) {
    long r = blockIdx.x;
    int h = (int)(r & 15);
    long row = r >> 4;
    int p = (int)(row & (SS - 1));
    const float* ptr = x + row * 2048 + h * 128;
    int f = threadIdx.x;

    float v = ptr[f];
    float ss = v * v;
#pragma unroll
    for (int o = 16; o; o >>= 1) ss += __shfl_xor_sync(0xffffffffu, ss, o);
    __shared__ float red[4];
    if ((f & 31) == 0) red[f >> 5] = ss;
    __syncthreads();
    ss = red[0] + red[1] + red[2] + red[3];

    float rms = sqrtf(ss * (1.f / 128.f));
    float sv = v / (rms + EPSV) * w[f];

    __shared__ float sh[128];
    __shared__ float sh2[128];
    sh[f] = sv;
    __syncthreads();

    int i = f & 63;
    float c = cosT[p * 64 + i], s = sinT[p * 64 + i];
    float out = (f < 64) ? (sv * c - sh[f + 64] * s) : (sv * c + sh[f - 64] * s);
    sh2[f] = out * scale;
    __syncthreads();

    if (f < 64) {
        uint32_t hi, lo;
        split_pair(sh2[2 * f], sh2[2 * f + 1], hi, lo);
        long o = row * 1024 + h * 64 + f;
        ohi[o] = hi;
        olo[o] = lo;
    }
}

// ---------------- V transpose + split --------------------------------------------
__global__ void v_tsplit_kernel(const float* __restrict__ v,
                                uint32_t* __restrict__ vthi, uint32_t* __restrict__ vtlo) {
    int b = blockIdx.z, pb = blockIdx.y, cb = blockIdx.x;
    __shared__ float ts[64][65];
    int tid = threadIdx.x;
#pragma unroll
    for (int i = 0; i < 16; i++) {
        int idx = i * 256 + tid;
        int r = idx >> 6, c = idx & 63;
        ts[r][c] = v[(long)(b * 2048 + pb * 64 + r) * 2048 + cb * 64 + c];
    }
    __syncthreads();
#pragma unroll
    for (int i = 0; i < 8; i++) {
        int idx = i * 256 + tid;
        int c = idx >> 5, pp = idx & 31;
        uint32_t hi, lo;
        split_pair(ts[2 * pp][c], ts[2 * pp + 1][c], hi, lo);
        long dst = (long)(b * 2048 + cb * 64 + c) * 1024 + pb * 32 + pp;
        vthi[dst] = hi;
        vtlo[dst] = lo;
    }
}

// ---------------- flash attention -------------------------------------------------
#define FL_KSLO 17408
#define FL_VSHI 34816
#define FL_VSLO 53248
#define FL_STAGE 71680
#define FL_SMEM  143360

__global__ __launch_bounds__(256, 1)
void flash_kernel(const uint32_t* __restrict__ qhi, const uint32_t* __restrict__ qlo,
                  const uint32_t* __restrict__ khi, const uint32_t* __restrict__ klo,
                  const uint32_t* __restrict__ vthi, const uint32_t* __restrict__ vtlo,
                  uint32_t* __restrict__ ahi, uint32_t* __restrict__ alo) {
    extern __shared__ char fsm[];
    const int tid = threadIdx.x;
    const int lane = tid & 31, warp = tid >> 5;
    const int g = lane >> 2, t4 = lane & 3;
    const int qt = blockIdx.x, bh = blockIdx.y;
    const int b = bh >> 4, h = bh & 15;
    const int wm = warp * 16;
    const long qr0 = (long)b * 2048 + qt * 128;

    const uint32_t smem_base = (uint32_t)__cvta_generic_to_shared(fsm);

    uint32_t qah[8][4], qal[8][4];
    {
        const uint32_t* qh0 = qhi + (qr0 + wm + g) * 1024 + h * 64;
        const uint32_t* qh8 = qhi + (qr0 + wm + g + 8) * 1024 + h * 64;
        const uint32_t* ql0 = qlo + (qr0 + wm + g) * 1024 + h * 64;
        const uint32_t* ql8 = qlo + (qr0 + wm + g + 8) * 1024 + h * 64;
#pragma unroll
        for (int fs = 0; fs < 8; fs++) {
            qah[fs][0] = qh0[8 * fs + t4];
            qah[fs][1] = qh8[8 * fs + t4];
            qah[fs][2] = qh0[8 * fs + 4 + t4];
            qah[fs][3] = qh8[8 * fs + 4 + t4];
            qal[fs][0] = ql0[8 * fs + t4];
            qal[fs][1] = ql8[8 * fs + t4];
            qal[fs][2] = ql0[8 * fs + 4 + t4];
            qal[fs][3] = ql8[8 * fs + 4 + t4];
        }
    }

    float acc_o[16][4];
#pragma unroll
    for (int nt = 0; nt < 16; nt++)
#pragma unroll
        for (int j = 0; j < 4; j++) acc_o[nt][j] = 0.f;
    float mrow[2] = {-1e30f, -1e30f};
    float lrow[2] = {0.f, 0.f};

    const uint32_t* khb = khi + ((long)b * 2048) * 1024 + h * 64;
    const uint32_t* klb = klo + ((long)b * 2048) * 1024 + h * 64;
    const uint32_t* vhb = vthi + ((long)b * 2048 + h * 128) * 1024;
    const uint32_t* vlb = vtlo + ((long)b * 2048 + h * 128) * 1024;

    auto prefetch = [&](int kb) {
        uint32_t sb = smem_base + (kb & 1) * FL_STAGE;
        const uint32_t* kh = khb + (long)kb * 64 * 1024;
        const uint32_t* kl = klb + (long)kb * 64 * 1024;
#pragma unroll
        for (int i = 0; i < 4; i++) {
            int c = tid + i * 256;
            int row = c >> 4, cc = (c & 15) * 4;
            cpa16(sb + (row * 68 + cc) * 4, kh + (long)row * 1024 + cc);
            cpa16(sb + FL_KSLO + (row * 68 + cc) * 4, kl + (long)row * 1024 + cc);
        }
#pragma unroll
        for (int i = 0; i < 4; i++) {
            int c = tid + i * 256;
            int col = c >> 3, ci = (c & 7) * 4;
            cpa16(sb + FL_VSHI + (col * 36 + ci) * 4, vhb + (long)col * 1024 + kb * 32 + ci);
            cpa16(sb + FL_VSLO + (col * 36 + ci) * 4, vlb + (long)col * 1024 + kb * 32 + ci);
        }
        asm volatile("cp.async.commit_group;\n" ::: "memory");
    };

    prefetch(0);

    for (int kb = 0; kb < 32; kb++) {
        if (kb + 1 < 32) {
            prefetch(kb + 1);
            asm volatile("cp.async.wait_group 1;\n" ::: "memory");
        } else {
            asm volatile("cp.async.wait_group 0;\n" ::: "memory");
        }
        __syncthreads();

        const uint32_t* ksh = (const uint32_t*)(fsm + (kb & 1) * FL_STAGE);
        const uint32_t* ksl = (const uint32_t*)(fsm + (kb & 1) * FL_STAGE + FL_KSLO);
        const uint32_t* vsh = (const uint32_t*)(fsm + (kb & 1) * FL_STAGE + FL_VSHI);
        const uint32_t* vsl = (const uint32_t*)(fsm + (kb & 1) * FL_STAGE + FL_VSLO);

        float sacc[8][4];
#pragma unroll
        for (int nt = 0; nt < 8; nt++)
#pragma unroll
            for (int j = 0; j < 4; j++) sacc[nt][j] = 0.f;

#pragma unroll
        for (int fs = 0; fs < 8; fs++) {
            uint32_t kb0h[8], kb1h[8], kb0l[8], kb1l[8];
#pragma unroll
            for (int nt = 0; nt < 8; nt++) {
                int o = (nt * 8 + g) * 68 + fs * 8 + t4;
                kb0h[nt] = ksh[o];
                kb1h[nt] = ksh[o + 4];
                kb0l[nt] = ksl[o];
                kb1l[nt] = ksl[o + 4];
            }
#pragma unroll
            for (int nt = 0; nt < 8; nt++) {
                mma16816(sacc[nt], qah[fs][0], qah[fs][1], qah[fs][2], qah[fs][3], kb0h[nt], kb1h[nt]);
                mma16816(sacc[nt], qah[fs][0], qah[fs][1], qah[fs][2], qah[fs][3], kb0l[nt], kb1l[nt]);
                mma16816(sacc[nt], qal[fs][0], qal[fs][1], qal[fs][2], qal[fs][3], kb0h[nt], kb1h[nt]);
            }
        }

#pragma unroll
        for (int r = 0; r < 2; r++) {
            float m_ = -1e30f;
#pragma unroll
            for (int nt = 0; nt < 8; nt++)
                m_ = fmaxf(m_, fmaxf(sacc[nt][2 * r], sacc[nt][2 * r + 1]));
            m_ = fmaxf(m_, __shfl_xor_sync(0xffffffffu, m_, 1));
            m_ = fmaxf(m_, __shfl_xor_sync(0xffffffffu, m_, 2));

            float mnew = fmaxf(mrow[r], m_);
            float scale = __expf(mrow[r] - mnew);
            mrow[r] = mnew;

            float rs = 0.f;
#pragma unroll
            for (int nt = 0; nt < 8; nt++) {
                float p0 = __expf(sacc[nt][2 * r] - mnew);
                float p1 = __expf(sacc[nt][2 * r + 1] - mnew);
                sacc[nt][2 * r] = p0;
                sacc[nt][2 * r + 1] = p1;
                rs += p0 + p1;
            }
            rs += __shfl_xor_sync(0xffffffffu, rs, 1);
            rs += __shfl_xor_sync(0xffffffffu, rs, 2);
            lrow[r] = lrow[r] * scale + rs;
#pragma unroll
            for (int nt = 0; nt < 16; nt++) {
                acc_o[nt][2 * r] *= scale;
                acc_o[nt][2 * r + 1] *= scale;
            }
        }

#pragma unroll
        for (int s = 0; s < 4; s++) {
            uint32_t ph[4], pl[4];
            {
                uint32_t h0, l0;
                split_pair(sacc[2 * s][0], sacc[2 * s][1], h0, l0);         ph[0] = h0; pl[0] = l0;
                split_pair(sacc[2 * s][2], sacc[2 * s][3], h0, l0);         ph[1] = h0; pl[1] = l0;
                split_pair(sacc[2 * s + 1][0], sacc[2 * s + 1][1], h0, l0); ph[2] = h0; pl[2] = l0;
                split_pair(sacc[2 * s + 1][2], sacc[2 * s + 1][3], h0, l0); ph[3] = h0; pl[3] = l0;
            }
#pragma unroll
            for (int nt = 0; nt < 16; nt++) {
                int o = (nt * 8 + g) * 36 + s * 8 + t4;
                uint32_t v0h = vsh[o], v1h = vsh[o + 4];
                uint32_t v0l = vsl[o], v1l = vsl[o + 4];
                mma16816(acc_o[nt], ph[0], ph[1], ph[2], ph[3], v0h, v1h);
                mma16816(acc_o[nt], pl[0], pl[1], pl[2], pl[3], v0h, v1h);
                mma16816(acc_o[nt], ph[0], ph[1], ph[2], ph[3], v0l, v1l);
            }
        }
        __syncthreads();
    }

    // ---- epilogue: normalize and store as split pairs ----
    float inv0 = 1.f / lrow[0];
    float inv1 = 1.f / lrow[1];
    long r0 = (qr0 + wm + g) * 1024 + h * 64;
    long r8 = (qr0 + wm + g + 8) * 1024 + h * 64;
#pragma unroll
    for (int nt = 0; nt < 16; nt++) {
        int pp = nt * 4 + t4;
        uint32_t hi, lo;
        split_pair(acc_o[nt][0] * inv0, acc_o[nt][1] * inv0, hi, lo);
        ahi[r0 + pp] = hi;
        alo[r0 + pp] = lo;
        split_pair(acc_o[nt][2] * inv1, acc_o[nt][3] * inv1, hi, lo);
        ahi[r8 + pp] = hi;
        alo[r8 + pp] = lo;
    }
}

// ---------------- host orchestration ----------------------------------------------
extern "C" void kernel_launch(void* const* d_in, const int* in_sizes, int n_in,
                              void* d_out, int out_size) {
    const float* xq = (const float*)d_in[0];
    const float* xk = (const float*)d_in[1];
    const float* xv = (const float*)d_in[2];
    const float* WQ = (const float*)d_in[3];
    const float* WK = (const float*)d_in[4];
    const float* WV = (const float*)d_in[5];
    const float* WO = (const float*)d_in[6];
    const float* bQ = (const float*)d_in[7];
    const float* bK = (const float*)d_in[8];
    const float* bV = (const float*)d_in[9];
    const float* bO = (const float*)d_in[10];
    const float* qw = (const float*)d_in[11];
    const float* kw = (const float*)d_in[12];
    float* out = (float*)d_out;

    float *qb, *kb, *vb, *ct, *st;
    uint32_t *xqhi, *xqlo, *xkhi, *xklo, *xvhi, *xvlo;
    uint32_t *w0hi, *w0lo, *w1hi, *w1lo, *w2hi, *w2lo, *wohi, *wolo;
    uint32_t *qhi, *qlo, *khi, *klo, *vthi, *vtlo, *ahi, *alo;
    cudaGetSymbolAddress((void**)&qb, g_q);
    cudaGetSymbolAddress((void**)&kb, g_k);
    cudaGetSymbolAddress((void**)&vb, g_v);
    cudaGetSymbolAddress((void**)&ct, g_cos);
    cudaGetSymbolAddress((void**)&st, g_sin);
    cudaGetSymbolAddress((void**)&xqhi, g_xqhi);
    cudaGetSymbolAddress((void**)&xqlo, g_xqlo);
    cudaGetSymbolAddress((void**)&xkhi, g_xkhi);
    cudaGetSymbolAddress((void**)&xklo, g_xklo);
    cudaGetSymbolAddress((void**)&xvhi, g_xvhi);
    cudaGetSymbolAddress((void**)&xvlo, g_xvlo);
    cudaGetSymbolAddress((void**)&w0hi, g_w0hi);
    cudaGetSymbolAddress((void**)&w0lo, g_w0lo);
    cudaGetSymbolAddress((void**)&w1hi, g_w1hi);
    cudaGetSymbolAddress((void**)&w1lo, g_w1lo);
    cudaGetSymbolAddress((void**)&w2hi, g_w2hi);
    cudaGetSymbolAddress((void**)&w2lo, g_w2lo);
    cudaGetSymbolAddress((void**)&wohi, g_wohi);
    cudaGetSymbolAddress((void**)&wolo, g_wolo);
    cudaGetSymbolAddress((void**)&qhi, g_qhi);
    cudaGetSymbolAddress((void**)&qlo, g_qlo);
    cudaGetSymbolAddress((void**)&khi, g_khi);
    cudaGetSymbolAddress((void**)&klo, g_klo);
    cudaGetSymbolAddress((void**)&vthi, g_vthi);
    cudaGetSymbolAddress((void**)&vtlo, g_vtlo);
    cudaGetSymbolAddress((void**)&ahi, g_ahi);
    cudaGetSymbolAddress((void**)&alo, g_alo);

    cudaFuncSetAttribute(flash_kernel, cudaFuncAttributeMaxDynamicSharedMemorySize, FL_SMEM);
    cudaFuncSetAttribute(bgemm2_kernel, cudaFuncAttributeMaxDynamicSharedMemorySize, G2_SMEM);

    rope_table_kernel<<<(2048 * 64 + 255) / 256, 256>>>(ct, st);

    // pre-split inputs + weights
    split_rows_kernel<<<16384, 256>>>(xq, xqhi, xqlo);
    split_rows_kernel<<<16384, 256>>>(xk, xkhi, xklo);
    split_rows_kernel<<<16384, 256>>>(xv, xvhi, xvlo);
    wsplit_kernel<<<8192, 256>>>(WQ, w0hi, w0lo);
    wsplit_kernel<<<8192, 256>>>(WK, w1hi, w1lo);
    wsplit_kernel<<<8192, 256>>>(WV, w2hi, w2lo);
    wosplit_kernel<<<8192, 256>>>(WO, wohi, wolo);

    // QKV projections (pipelined, conversion-free)
    dim3 gProj(16, 32);
    bgemm2_kernel<<<gProj, 256, G2_SMEM>>>(xqhi, xqlo, w0hi, w0lo, qb, bQ, 4096, 2048, 2048);
    bgemm2_kernel<<<gProj, 256, G2_SMEM>>>(xkhi, xklo, w1hi, w1lo, kb, bK, 4096, 2048, 2048);
    bgemm2_kernel<<<gProj, 256, G2_SMEM>>>(xvhi, xvlo, w2hi, w2lo, vb, bV, 4096, 2048, 2048);

    // RMSNorm + RoPE + split (q scaled by 1/sqrt(F))
    norm_rope_split_kernel<<<BB * SS * HH, 128>>>(qb, qw, ct, st, qhi, qlo, 0.08838834764831845f);
    norm_rope_split_kernel<<<BB * SS * HH, 128>>>(kb, kw, ct, st, khi, klo, 1.f);

    // V transpose + split
    dim3 gV(32, 32, 2);
    v_tsplit_kernel<<<gV, 256>>>(vb, vthi, vtlo);

    // flash attention -> split pair output
    dim3 gF(16, 32);
    flash_kernel<<<gF, 256, FL_SMEM>>>(qhi, qlo, khi, klo, vthi, vtlo, ahi, alo);

    // output projection
    bgemm2_kernel<<<gProj, 256, G2_SMEM>>>(ahi, alo, wohi, wolo, out, bO, 4096, 2048, 2048);
}

// round 8
// speedup vs baseline: 3.0558x; 1.0555x over previous
#include <cuda_runtime.h>
#include <cuda_bf16.h>
#include <cstdint>
#include <math.h>

#define BB 2
#define SS 2048
#define DD 2048
#define HH 16
#define FF 128
#define EPSV 1e-6f

// q prescale: (1/sqrt(128)) * log2(e)  -> scores already in log2 units
#define QSCALE 0.1275174431f
// fixed softmax offset in log2 units; |score_log2| <= 128/sqrt(128)*log2e = 16.33
#define SOFF 16.5f

// ---------------- scratch (static device memory; no allocations) ----------------
__device__ float g_q[4096 * 2048];
__device__ float g_k[4096 * 2048];
__device__ float g_v[4096 * 2048];
__device__ float g_cos[2048 * 64];
__device__ float g_sin[2048 * 64];
// x inputs pre-split: [row 4096][kpair 1024]
__device__ uint32_t g_xqhi[4096 * 1024];
__device__ uint32_t g_xqlo[4096 * 1024];
__device__ uint32_t g_xkhi[4096 * 1024];
__device__ uint32_t g_xklo[4096 * 1024];
__device__ uint32_t g_xvhi[4096 * 1024];
__device__ uint32_t g_xvlo[4096 * 1024];
// transposed+split weights: [kpair 1024][n 2048]
__device__ uint32_t g_w0hi[1024 * 2048];
__device__ uint32_t g_w0lo[1024 * 2048];
__device__ uint32_t g_w1hi[1024 * 2048];
__device__ uint32_t g_w1lo[1024 * 2048];
__device__ uint32_t g_w2hi[1024 * 2048];
__device__ uint32_t g_w2lo[1024 * 2048];
__device__ uint32_t g_wohi[1024 * 2048];
__device__ uint32_t g_wolo[1024 * 2048];
// normed q/k split pairs: [row 4096][pair 1024]
__device__ uint32_t g_qhi[4096 * 1024];
__device__ uint32_t g_qlo[4096 * 1024];
__device__ uint32_t g_khi[4096 * 1024];
__device__ uint32_t g_klo[4096 * 1024];
// V transposed split: [b*2048 + h*128 + f][ppair 1024]
__device__ uint32_t g_vthi[2 * 2048 * 1024];
__device__ uint32_t g_vtlo[2 * 2048 * 1024];
// attention output split pairs: [row 4096][hf-pair 1024]
__device__ uint32_t g_ahi[4096 * 1024];
__device__ uint32_t g_alo[4096 * 1024];

// ---------------- helpers ---------------------------------------------------------
__device__ __forceinline__ uint32_t pack2(__nv_bfloat16 a, __nv_bfloat16 b) {
    __nv_bfloat162 h2;
    h2.x = a; h2.y = b;
    return *reinterpret_cast<uint32_t*>(&h2);
}

__device__ __forceinline__ void split_pair(float e0, float e1, uint32_t& hi, uint32_t& lo) {
    __nv_bfloat16 h0 = __float2bfloat16_rn(e0);
    __nv_bfloat16 h1 = __float2bfloat16_rn(e1);
    float l0 = e0 - __bfloat162float(h0);
    float l1 = e1 - __bfloat162float(h1);
    hi = pack2(h0, h1);
    lo = pack2(__float2bfloat16_rn(l0), __float2bfloat16_rn(l1));
}

__device__ __forceinline__ float fexp2(float x) {
    float r;
    asm("ex2.approx.f32 %0, %1;" : "=f"(r) : "f"(x));
    return r;
}

__device__ __forceinline__ void mma16816(float* c, uint32_t a0, uint32_t a1, uint32_t a2,
                                         uint32_t a3, uint32_t b0, uint32_t b1) {
    asm volatile(
        "mma.sync.aligned.m16n8k16.row.col.f32.bf16.bf16.f32 "
        "{%0,%1,%2,%3},{%4,%5,%6,%7},{%8,%9},{%0,%1,%2,%3};\n"
        : "+f"(c[0]), "+f"(c[1]), "+f"(c[2]), "+f"(c[3])
        : "r"(a0), "r"(a1), "r"(a2), "r"(a3), "r"(b0), "r"(b1));
}

__device__ __forceinline__ void cpa16(uint32_t dst, const void* src) {
    asm volatile("cp.async.cg.shared.global [%0], [%1], 16;\n" :: "r"(dst), "l"(src));
}

// ---------------- RoPE table -----------------------------------------------------
__global__ void rope_table_kernel(float* __restrict__ cosT, float* __restrict__ sinT) {
    int idx = blockIdx.x * 256 + threadIdx.x;
    if (idx >= 2048 * 64) return;
    int p = idx / 64, i = idx % 64;
    float freq = (float)(1.0 / pow(10000.0, (double)i / 64.0));
    float a = (float)p * freq;
    cosT[idx] = (float)cos((double)a);
    sinT[idx] = (float)sin((double)a);
}

// ---------------- pre-split kernels ----------------------------------------------
__global__ void split_rows3_kernel(const float* __restrict__ x0, const float* __restrict__ x1,
                                   const float* __restrict__ x2,
                                   uint32_t* __restrict__ h0, uint32_t* __restrict__ l0,
                                   uint32_t* __restrict__ h1, uint32_t* __restrict__ l1,
                                   uint32_t* __restrict__ h2, uint32_t* __restrict__ l2) {
    int s = blockIdx.z;
    const float* x = (s == 0) ? x0 : (s == 1) ? x1 : x2;
    uint32_t* xh = (s == 0) ? h0 : (s == 1) ? h1 : h2;
    uint32_t* xl = (s == 0) ? l0 : (s == 1) ? l1 : l2;
    int idx = blockIdx.x * 256 + threadIdx.x;
    float2 v = ((const float2*)x)[idx];
    uint32_t hi, lo;
    split_pair(v.x, v.y, hi, lo);
    xh[idx] = hi;
    xl[idx] = lo;
}

// W[h,d,f] -> pairs over d: [kp=d/2][n=h*128+f]; z batches 3 weights
__global__ void wsplit3_kernel(const float* __restrict__ W0, const float* __restrict__ W1,
                               const float* __restrict__ W2,
                               uint32_t* __restrict__ h0, uint32_t* __restrict__ l0,
                               uint32_t* __restrict__ h1, uint32_t* __restrict__ l1,
                               uint32_t* __restrict__ h2, uint32_t* __restrict__ l2) {
    int s = blockIdx.z;
    const float* W = (s == 0) ? W0 : (s == 1) ? W1 : W2;
    uint32_t* wh = (s == 0) ? h0 : (s == 1) ? h1 : h2;
    uint32_t* wl = (s == 0) ? l0 : (s == 1) ? l1 : l2;
    int idx = blockIdx.x * 256 + threadIdx.x;
    int kp = idx >> 11, n = idx & 2047;
    int h = n >> 7, f = n & 127;
    float a = W[((long)h * 2048 + 2 * kp) * 128 + f];
    float b = W[((long)h * 2048 + 2 * kp + 1) * 128 + f];
    uint32_t hi, lo;
    split_pair(a, b, hi, lo);
    wh[idx] = hi;
    wl[idx] = lo;
}

// WO[hf][m] -> pairs over hf: [kp=hf/2][m]
__global__ void wosplit_kernel(const float* __restrict__ WO,
                               uint32_t* __restrict__ whi, uint32_t* __restrict__ wlo) {
    int idx = blockIdx.x * 256 + threadIdx.x;
    int kp = idx >> 11, m = idx & 2047;
    float a = WO[(long)(2 * kp) * 2048 + m];
    float b = WO[(long)(2 * kp + 1) * 2048 + m];
    uint32_t hi, lo;
    split_pair(a, b, hi, lo);
    whi[idx] = hi;
    wlo[idx] = lo;
}

// ---------------- pipelined split-bf16 GEMM on pre-split pair arrays -------------
#define G2_AS_LO 10240
#define G2_BS_HI 20480
#define G2_BS_LO 29184
#define G2_STAGE 37888
#define G2_SMEM  75776

template <int NSET>
__global__ __launch_bounds__(256, 2)
void bgemm2_kernel(const uint32_t* __restrict__ A0hi, const uint32_t* __restrict__ A0lo,
                   const uint32_t* __restrict__ B0hi, const uint32_t* __restrict__ B0lo,
                   float* __restrict__ C0, const float* __restrict__ bias0,
                   const uint32_t* A1hi, const uint32_t* A1lo,
                   const uint32_t* B1hi, const uint32_t* B1lo,
                   float* C1, const float* bias1,
                   const uint32_t* A2hi, const uint32_t* A2lo,
                   const uint32_t* B2hi, const uint32_t* B2lo,
                   float* C2, const float* bias2) {
    extern __shared__ char gsm[];
    const uint32_t smem_base = (uint32_t)__cvta_generic_to_shared(gsm);

    const uint32_t* Ahi = A0hi;
    const uint32_t* Alo = A0lo;
    const uint32_t* Bhi = B0hi;
    const uint32_t* Blo = B0lo;
    float* C = C0;
    const float* bias = bias0;
    if (NSET > 1) {
        int s = blockIdx.z;
        if (s == 1) { Ahi = A1hi; Alo = A1lo; Bhi = B1hi; Blo = B1lo; C = C1; bias = bias1; }
        else if (s == 2) { Ahi = A2hi; Alo = A2lo; Bhi = B2hi; Blo = B2lo; C = C2; bias = bias2; }
    }

    const int tid = threadIdx.x;
    const int lane = tid & 31;
    const int warp = tid >> 5;
    const int wm = (warp >> 2) * 64;
    const int wn = (warp & 3) * 32;
    const int g = lane >> 2;
    const int t4 = lane & 3;
    const int bm = blockIdx.y * 128, bn = blockIdx.x * 128;

    float acc[4][4][4];
#pragma unroll
    for (int i = 0; i < 4; i++)
#pragma unroll
        for (int j = 0; j < 4; j++)
#pragma unroll
            for (int r = 0; r < 4; r++) acc[i][j][r] = 0.f;

    auto prefetch = [&](int t) {
        uint32_t sb = smem_base + (t & 1) * G2_STAGE;
#pragma unroll
        for (int i = 0; i < 2; i++) {
            int c = tid + i * 256;
            int row = c >> 2, q4 = (c & 3) * 4;
            const uint32_t* sh = Ahi + (long)(bm + row) * 1024 + t * 16 + q4;
            const uint32_t* sl = Alo + (long)(bm + row) * 1024 + t * 16 + q4;
            cpa16(sb + (row * 20 + q4) * 4, sh);
            cpa16(sb + G2_AS_LO + (row * 20 + q4) * 4, sl);
        }
#pragma unroll
        for (int i = 0; i < 2; i++) {
            int c = tid + i * 256;
            int kp = c >> 5, n4 = (c & 31) * 4;
            const uint32_t* sh = Bhi + (long)(t * 16 + kp) * 2048 + bn + n4;
            const uint32_t* sl = Blo + (long)(t * 16 + kp) * 2048 + bn + n4;
            cpa16(sb + G2_BS_HI + (kp * 136 + n4) * 4, sh);
            cpa16(sb + G2_BS_LO + (kp * 136 + n4) * 4, sl);
        }
        asm volatile("cp.async.commit_group;\n" ::: "memory");
    };

    prefetch(0);

    for (int t = 0; t < 64; t++) {
        if (t + 1 < 64) {
            prefetch(t + 1);
            asm volatile("cp.async.wait_group 1;\n" ::: "memory");
        } else {
            asm volatile("cp.async.wait_group 0;\n" ::: "memory");
        }
        __syncthreads();

        const uint32_t* ash = (const uint32_t*)(gsm + (t & 1) * G2_STAGE);
        const uint32_t* asl = (const uint32_t*)(gsm + (t & 1) * G2_STAGE + G2_AS_LO);
        const uint32_t* bsh = (const uint32_t*)(gsm + (t & 1) * G2_STAGE + G2_BS_HI);
        const uint32_t* bsl = (const uint32_t*)(gsm + (t & 1) * G2_STAGE + G2_BS_LO);

#pragma unroll
        for (int ks = 0; ks < 2; ks++) {
            const int kp0 = ks * 8 + t4;
            uint32_t bh0[4], bh1[4], bl0[4], bl1[4];
#pragma unroll
            for (int ct = 0; ct < 4; ct++) {
                int col = wn + ct * 8 + g;
                bh0[ct] = bsh[kp0 * 136 + col];
                bh1[ct] = bsh[(kp0 + 4) * 136 + col];
                bl0[ct] = bsl[kp0 * 136 + col];
                bl1[ct] = bsl[(kp0 + 4) * 136 + col];
            }
#pragma unroll
            for (int rt = 0; rt < 4; rt++) {
                int row = wm + rt * 16 + g;
                uint32_t ah0 = ash[row * 20 + kp0];
                uint32_t ah1 = ash[(row + 8) * 20 + kp0];
                uint32_t ah2 = ash[row * 20 + kp0 + 4];
                uint32_t ah3 = ash[(row + 8) * 20 + kp0 + 4];
                uint32_t al0 = asl[row * 20 + kp0];
                uint32_t al1 = asl[(row + 8) * 20 + kp0];
                uint32_t al2 = asl[row * 20 + kp0 + 4];
                uint32_t al3 = asl[(row + 8) * 20 + kp0 + 4];
#pragma unroll
                for (int ct = 0; ct < 4; ct++) {
                    mma16816(acc[rt][ct], ah0, ah1, ah2, ah3, bh0[ct], bh1[ct]);
                    mma16816(acc[rt][ct], ah0, ah1, ah2, ah3, bl0[ct], bl1[ct]);
                    mma16816(acc[rt][ct], al0, al1, al2, al3, bh0[ct], bh1[ct]);
                }
            }
        }
        __syncthreads();
    }

#pragma unroll
    for (int rt = 0; rt < 4; rt++) {
        int row0 = bm + wm + rt * 16 + g;
#pragma unroll
        for (int ct = 0; ct < 4; ct++) {
            int col0 = bn + wn + ct * 8 + 2 * t4;
            float b0 = bias ? bias[col0] : 0.f;
            float b1 = bias ? bias[col0 + 1] : 0.f;
            float2 v0 = make_float2(acc[rt][ct][0] + b0, acc[rt][ct][1] + b1);
            float2 v1 = make_float2(acc[rt][ct][2] + b0, acc[rt][ct][3] + b1);
            *(float2*)(C + (long)row0 * 2048 + col0) = v0;
            *(float2*)(C + (long)(row0 + 8) * 2048 + col0) = v1;
        }
    }
}

// ---------------- fused RMSNorm + RoPE -> split pairs (q and k in one launch) ----
__global__ void norm_rope_split_kernel(const float* __restrict__ xq, const float* __restrict__ xk,
                                       const float* __restrict__ wq, const float* __restrict__ wk,
                                       const float* __restrict__ cosT, const float* __restrict__ sinT,
                                       uint32_t* __restrict__ qhi, uint32_t* __restrict__ qlo,
                                       uint32_t* __restrict__ khi, uint32_t* __restrict__ klo) {
    int which = blockIdx.y;
    const float* x = which ? xk : xq;
    const float* w = which ? wk : wq;
    uint32_t* ohi = which ? khi : qhi;
    uint32_t* olo = which ? klo : qlo;
    float scale = which ? 1.f : QSCALE;

    long r = blockIdx.x;
    int h = (int)(r & 15);
    long row = r >> 4;
    int p = (int)(row & (SS - 1));
    const float* ptr = x + row * 2048 + h * 128;
    int f = threadIdx.x;

    float v = ptr[f];
    float ss = v * v;
#pragma unroll
    for (int o = 16; o; o >>= 1) ss += __shfl_xor_sync(0xffffffffu, ss, o);
    __shared__ float red[4];
    if ((f & 31) == 0) red[f >> 5] = ss;
    __syncthreads();
    ss = red[0] + red[1] + red[2] + red[3];

    float rms = sqrtf(ss * (1.f / 128.f));
    float sv = v / (rms + EPSV) * w[f];

    __shared__ float sh[128];
    __shared__ float sh2[128];
    sh[f] = sv;
    __syncthreads();

    int i = f & 63;
    float c = cosT[p * 64 + i], s = sinT[p * 64 + i];
    float out = (f < 64) ? (sv * c - sh[f + 64] * s) : (sv * c + sh[f - 64] * s);
    sh2[f] = out * scale;
    __syncthreads();

    if (f < 64) {
        uint32_t hi, lo;
        split_pair(sh2[2 * f], sh2[2 * f + 1], hi, lo);
        long o = row * 1024 + h * 64 + f;
        ohi[o] = hi;
        olo[o] = lo;
    }
}

// ---------------- V transpose + split --------------------------------------------
__global__ void v_tsplit_kernel(const float* __restrict__ v,
                                uint32_t* __restrict__ vthi, uint32_t* __restrict__ vtlo) {
    int b = blockIdx.z, pb = blockIdx.y, cb = blockIdx.x;
    __shared__ float ts[64][65];
    int tid = threadIdx.x;
#pragma unroll
    for (int i = 0; i < 16; i++) {
        int idx = i * 256 + tid;
        int r = idx >> 6, c = idx & 63;
        ts[r][c] = v[(long)(b * 2048 + pb * 64 + r) * 2048 + cb * 64 + c];
    }
    __syncthreads();
#pragma unroll
    for (int i = 0; i < 8; i++) {
        int idx = i * 256 + tid;
        int c = idx >> 5, pp = idx & 31;
        uint32_t hi, lo;
        split_pair(ts[2 * pp][c], ts[2 * pp + 1][c], hi, lo);
        long dst = (long)(b * 2048 + cb * 64 + c) * 1024 + pb * 32 + pp;
        vthi[dst] = hi;
        vtlo[dst] = lo;
    }
}

// ---------------- flash attention (fixed-offset softmax, no max tracking) --------
#define FL_KSLO 17408
#define FL_VSHI 34816
#define FL_VSLO 53248
#define FL_STAGE 71680
#define FL_SMEM  143360

__global__ __launch_bounds__(256, 1)
void flash_kernel(const uint32_t* __restrict__ qhi, const uint32_t* __restrict__ qlo,
                  const uint32_t* __restrict__ khi, const uint32_t* __restrict__ klo,
                  const uint32_t* __restrict__ vthi, const uint32_t* __restrict__ vtlo,
                  uint32_t* __restrict__ ahi, uint32_t* __restrict__ alo) {
    extern __shared__ char fsm[];
    const int tid = threadIdx.x;
    const int lane = tid & 31, warp = tid >> 5;
    const int g = lane >> 2, t4 = lane & 3;
    const int qt = blockIdx.x, bh = blockIdx.y;
    const int b = bh >> 4, h = bh & 15;
    const int wm = warp * 16;
    const long qr0 = (long)b * 2048 + qt * 128;

    const uint32_t smem_base = (uint32_t)__cvta_generic_to_shared(fsm);

    uint32_t qah[8][4], qal[8][4];
    {
        const uint32_t* qh0 = qhi + (qr0 + wm + g) * 1024 + h * 64;
        const uint32_t* qh8 = qhi + (qr0 + wm + g + 8) * 1024 + h * 64;
        const uint32_t* ql0 = qlo + (qr0 + wm + g) * 1024 + h * 64;
        const uint32_t* ql8 = qlo + (qr0 + wm + g + 8) * 1024 + h * 64;
#pragma unroll
        for (int fs = 0; fs < 8; fs++) {
            qah[fs][0] = qh0[8 * fs + t4];
            qah[fs][1] = qh8[8 * fs + t4];
            qah[fs][2] = qh0[8 * fs + 4 + t4];
            qah[fs][3] = qh8[8 * fs + 4 + t4];
            qal[fs][0] = ql0[8 * fs + t4];
            qal[fs][1] = ql8[8 * fs + t4];
            qal[fs][2] = ql0[8 * fs + 4 + t4];
            qal[fs][3] = ql8[8 * fs + 4 + t4];
        }
    }

    float acc_o[16][4];
#pragma unroll
    for (int nt = 0; nt < 16; nt++)
#pragma unroll
        for (int j = 0; j < 4; j++) acc_o[nt][j] = 0.f;
    float lrow[2] = {0.f, 0.f};

    const uint32_t* khb = khi + ((long)b * 2048) * 1024 + h * 64;
    const uint32_t* klb = klo + ((long)b * 2048) * 1024 + h * 64;
    const uint32_t* vhb = vthi + ((long)b * 2048 + h * 128) * 1024;
    const uint32_t* vlb = vtlo + ((long)b * 2048 + h * 128) * 1024;

    auto prefetch = [&](int kb) {
        uint32_t sb = smem_base + (kb & 1) * FL_STAGE;
        const uint32_t* kh = khb + (long)kb * 64 * 1024;
        const uint32_t* kl = klb + (long)kb * 64 * 1024;
#pragma unroll
        for (int i = 0; i < 4; i++) {
            int c = tid + i * 256;
            int row = c >> 4, cc = (c & 15) * 4;
            cpa16(sb + (row * 68 + cc) * 4, kh + (long)row * 1024 + cc);
            cpa16(sb + FL_KSLO + (row * 68 + cc) * 4, kl + (long)row * 1024 + cc);
        }
#pragma unroll
        for (int i = 0; i < 4; i++) {
            int c = tid + i * 256;
            int col = c >> 3, ci = (c & 7) * 4;
            cpa16(sb + FL_VSHI + (col * 36 + ci) * 4, vhb + (long)col * 1024 + kb * 32 + ci);
            cpa16(sb + FL_VSLO + (col * 36 + ci) * 4, vlb + (long)col * 1024 + kb * 32 + ci);
        }
        asm volatile("cp.async.commit_group;\n" ::: "memory");
    };

    prefetch(0);

    for (int kb = 0; kb < 32; kb++) {
        if (kb + 1 < 32) {
            prefetch(kb + 1);
            asm volatile("cp.async.wait_group 1;\n" ::: "memory");
        } else {
            asm volatile("cp.async.wait_group 0;\n" ::: "memory");
        }
        __syncthreads();

        const uint32_t* ksh = (const uint32_t*)(fsm + (kb & 1) * FL_STAGE);
        const uint32_t* ksl = (const uint32_t*)(fsm + (kb & 1) * FL_STAGE + FL_KSLO);
        const uint32_t* vsh = (const uint32_t*)(fsm + (kb & 1) * FL_STAGE + FL_VSHI);
        const uint32_t* vsl = (const uint32_t*)(fsm + (kb & 1) * FL_STAGE + FL_VSLO);

        // ---- S = Q @ K^T (scores already in log2 units via QSCALE) ----
        float sacc[8][4];
#pragma unroll
        for (int nt = 0; nt < 8; nt++)
#pragma unroll
            for (int j = 0; j < 4; j++) sacc[nt][j] = 0.f;

#pragma unroll
        for (int fs = 0; fs < 8; fs++) {
            uint32_t kb0h[8], kb1h[8], kb0l[8], kb1l[8];
#pragma unroll
            for (int nt = 0; nt < 8; nt++) {
                int o = (nt * 8 + g) * 68 + fs * 8 + t4;
                kb0h[nt] = ksh[o];
                kb1h[nt] = ksh[o + 4];
                kb0l[nt] = ksl[o];
                kb1l[nt] = ksl[o + 4];
            }
#pragma unroll
            for (int nt = 0; nt < 8; nt++) {
                mma16816(sacc[nt], qah[fs][0], qah[fs][1], qah[fs][2], qah[fs][3], kb0h[nt], kb1h[nt]);
                mma16816(sacc[nt], qah[fs][0], qah[fs][1], qah[fs][2], qah[fs][3], kb0l[nt], kb1l[nt]);
                mma16816(sacc[nt], qal[fs][0], qal[fs][1], qal[fs][2], qal[fs][3], kb0h[nt], kb1h[nt]);
            }
        }

        // ---- fixed-offset softmax: p = 2^(s - SOFF); no max, no rescale ----
#pragma unroll
        for (int r = 0; r < 2; r++) {
            float rs = 0.f;
#pragma unroll
            for (int nt = 0; nt < 8; nt++) {
                float p0 = fexp2(sacc[nt][2 * r] - SOFF);
                float p1 = fexp2(sacc[nt][2 * r + 1] - SOFF);
                sacc[nt][2 * r] = p0;
                sacc[nt][2 * r + 1] = p1;
                rs += p0 + p1;
            }
            rs += __shfl_xor_sync(0xffffffffu, rs, 1);
            rs += __shfl_xor_sync(0xffffffffu, rs, 2);
            lrow[r] += rs;
        }

        // ---- O += P @ V, 3-pass split ----
#pragma unroll
        for (int s = 0; s < 4; s++) {
            uint32_t ph[4], pl[4];
            {
                uint32_t h0, l0;
                split_pair(sacc[2 * s][0], sacc[2 * s][1], h0, l0);         ph[0] = h0; pl[0] = l0;
                split_pair(sacc[2 * s][2], sacc[2 * s][3], h0, l0);         ph[1] = h0; pl[1] = l0;
                split_pair(sacc[2 * s + 1][0], sacc[2 * s + 1][1], h0, l0); ph[2] = h0; pl[2] = l0;
                split_pair(sacc[2 * s + 1][2], sacc[2 * s + 1][3], h0, l0); ph[3] = h0; pl[3] = l0;
            }
#pragma unroll
            for (int nt = 0; nt < 16; nt++) {
                int o = (nt * 8 + g) * 36 + s * 8 + t4;
                uint32_t v0h = vsh[o], v1h = vsh[o + 4];
                uint32_t v0l = vsl[o], v1l = vsl[o + 4];
                mma16816(acc_o[nt], ph[0], ph[1], ph[2], ph[3], v0h, v1h);
                mma16816(acc_o[nt], pl[0], pl[1], pl[2], pl[3], v0h, v1h);
                mma16816(acc_o[nt], ph[0], ph[1], ph[2], ph[3], v0l, v1l);
            }
        }
        __syncthreads();
    }

    float inv0 = 1.f / lrow[0];
    float inv1 = 1.f / lrow[1];
    long r0 = (qr0 + wm + g) * 1024 + h * 64;
    long r8 = (qr0 + wm + g + 8) * 1024 + h * 64;
#pragma unroll
    for (int nt = 0; nt < 16; nt++) {
        int pp = nt * 4 + t4;
        uint32_t hi, lo;
        split_pair(acc_o[nt][0] * inv0, acc_o[nt][1] * inv0, hi, lo);
        ahi[r0 + pp] = hi;
        alo[r0 + pp] = lo;
        split_pair(acc_o[nt][2] * inv1, acc_o[nt][3] * inv1, hi, lo);
        ahi[r8 + pp] = hi;
        alo[r8 + pp] = lo;
    }
}

// ---------------- host orchestration ----------------------------------------------
extern "C" void kernel_launch(void* const* d_in, const int* in_sizes, int n_in,
                              void* d_out, int out_size) {
    const float* xq = (const float*)d_in[0];
    const float* xk = (const float*)d_in[1];
    const float* xv = (const float*)d_in[2];
    const float* WQ = (const float*)d_in[3];
    const float* WK = (const float*)d_in[4];
    const float* WV = (const float*)d_in[5];
    const float* WO = (const float*)d_in[6];
    const float* bQ = (const float*)d_in[7];
    const float* bK = (const float*)d_in[8];
    const float* bV = (const float*)d_in[9];
    const float* bO = (const float*)d_in[10];
    const float* qw = (const float*)d_in[11];
    const float* kw = (const float*)d_in[12];
    float* out = (float*)d_out;

    float *qb, *kb, *vb, *ct, *st;
    uint32_t *xqhi, *xqlo, *xkhi, *xklo, *xvhi, *xvlo;
    uint32_t *w0hi, *w0lo, *w1hi, *w1lo, *w2hi, *w2lo, *wohi, *wolo;
    uint32_t *qhi, *qlo, *khi, *klo, *vthi, *vtlo, *ahi, *alo;
    cudaGetSymbolAddress((void**)&qb, g_q);
    cudaGetSymbolAddress((void**)&kb, g_k);
    cudaGetSymbolAddress((void**)&vb, g_v);
    cudaGetSymbolAddress((void**)&ct, g_cos);
    cudaGetSymbolAddress((void**)&st, g_sin);
    cudaGetSymbolAddress((void**)&xqhi, g_xqhi);
    cudaGetSymbolAddress((void**)&xqlo, g_xqlo);
    cudaGetSymbolAddress((void**)&xkhi, g_xkhi);
    cudaGetSymbolAddress((void**)&xklo, g_xklo);
    cudaGetSymbolAddress((void**)&xvhi, g_xvhi);
    cudaGetSymbolAddress((void**)&xvlo, g_xvlo);
    cudaGetSymbolAddress((void**)&w0hi, g_w0hi);
    cudaGetSymbolAddress((void**)&w0lo, g_w0lo);
    cudaGetSymbolAddress((void**)&w1hi, g_w1hi);
    cudaGetSymbolAddress((void**)&w1lo, g_w1lo);
    cudaGetSymbolAddress((void**)&w2hi, g_w2hi);
    cudaGetSymbolAddress((void**)&w2lo, g_w2lo);
    cudaGetSymbolAddress((void**)&wohi, g_wohi);
    cudaGetSymbolAddress((void**)&wolo, g_wolo);
    cudaGetSymbolAddress((void**)&qhi, g_qhi);
    cudaGetSymbolAddress((void**)&qlo, g_qlo);
    cudaGetSymbolAddress((void**)&khi, g_khi);
    cudaGetSymbolAddress((void**)&klo, g_klo);
    cudaGetSymbolAddress((void**)&vthi, g_vthi);
    cudaGetSymbolAddress((void**)&vtlo, g_vtlo);
    cudaGetSymbolAddress((void**)&ahi, g_ahi);
    cudaGetSymbolAddress((void**)&alo, g_alo);

    cudaFuncSetAttribute(flash_kernel, cudaFuncAttributeMaxDynamicSharedMemorySize, FL_SMEM);
    cudaFuncSetAttribute(bgemm2_kernel<3>, cudaFuncAttributeMaxDynamicSharedMemorySize, G2_SMEM);
    cudaFuncSetAttribute(bgemm2_kernel<1>, cudaFuncAttributeMaxDynamicSharedMemorySize, G2_SMEM);

    rope_table_kernel<<<(2048 * 64 + 255) / 256, 256>>>(ct, st);

    // pre-split inputs + weights (batched launches)
    dim3 gS(16384, 1, 3);
    split_rows3_kernel<<<gS, 256>>>(xq, xk, xv, xqhi, xqlo, xkhi, xklo, xvhi, xvlo);
    dim3 gW(8192, 1, 3);
    wsplit3_kernel<<<gW, 256>>>(WQ, WK, WV, w0hi, w0lo, w1hi, w1lo, w2hi, w2lo);
    wosplit_kernel<<<8192, 256>>>(WO, wohi, wolo);

    // QKV projections: one batched launch
    dim3 gProj3(16, 32, 3);
    bgemm2_kernel<3><<<gProj3, 256, G2_SMEM>>>(
        xqhi, xqlo, w0hi, w0lo, qb, bQ,
        xkhi, xklo, w1hi, w1lo, kb, bK,
        xvhi, xvlo, w2hi, w2lo, vb, bV);

    // RMSNorm + RoPE + split (q scaled by QSCALE = 1/sqrt(F)*log2e)
    dim3 gNR(BB * SS * HH, 2);
    norm_rope_split_kernel<<<gNR, 128>>>(qb, kb, qw, kw, ct, st, qhi, qlo, khi, klo);

    // V transpose + split
    dim3 gV(32, 32, 2);
    v_tsplit_kernel<<<gV, 256>>>(vb, vthi, vtlo);

    // flash attention -> split pair output
    dim3 gF(16, 32);
    flash_kernel<<<gF, 256, FL_SMEM>>>(qhi, qlo, khi, klo, vthi, vtlo, ahi, alo);

    // output projection
    dim3 gProj(16, 32, 1);
    bgemm2_kernel<1><<<gProj, 256, G2_SMEM>>>(
        ahi, alo, wohi, wolo, out, bO,
        nullptr, nullptr, nullptr, nullptr, nullptr, nullptr,
        nullptr, nullptr, nullptr, nullptr, nullptr, nullptr);
}